// round 8
// baseline (speedup 1.0000x reference)
#include <cuda_runtime.h>
#include <cuda_bf16.h>

#define Bq   8
#define Tq   4096
#define DINq 1024
#define DMq  256
#define NCq  157

// ---------------------------------------------------------------------------
// Scratch: activations in [B, T, C] (K-major for MMA B operand)
// GEMM inputs (out, h, xt): separate bf16 hi/lo planes (pre-split for cp.async)
// qkv (GEMM output -> attention only): packed uint32 = hi | lo<<16
// ---------------------------------------------------------------------------
__device__ __nv_bfloat16 g_xh  [Bq * Tq * DINq];
__device__ __nv_bfloat16 g_xl  [Bq * Tq * DINq];
__device__ __nv_bfloat16 g_oh  [Bq * Tq * DMq];
__device__ __nv_bfloat16 g_ol  [Bq * Tq * DMq];
__device__ unsigned      g_qkvp[Bq * Tq * 3 * DMq];
__device__ __nv_bfloat16 g_hh  [Bq * Tq * DMq];
__device__ __nv_bfloat16 g_hl  [Bq * Tq * DMq];

// Weights split hi/lo, packed: b0w(256x1024), per layer wq|wk|wv|bw, b6w(157x256)
#define W_B0    0
#define W_L0    262144
#define W_PERL  (4 * 65536)
#define W_B6    (262144 + 5 * W_PERL)
#define W_TOTAL (W_B6 + NCq * DMq)
__device__ __nv_bfloat16 g_wh[W_TOTAL];
__device__ __nv_bfloat16 g_wl[W_TOTAL];

// ---------------------------------------------------------------------------
// Helpers
// ---------------------------------------------------------------------------
__device__ __forceinline__ unsigned smem_u32(const void* p) {
    unsigned a;
    asm("{ .reg .u64 t; cvta.to.shared.u64 t, %1; cvt.u32.u64 %0, t; }" : "=r"(a) : "l"(p));
    return a;
}
__device__ __forceinline__ void split1(float v, __nv_bfloat16& h, __nv_bfloat16& l) {
    h = __float2bfloat16_rn(v);
    l = __float2bfloat16_rn(v - __bfloat162float(h));
}
__device__ __forceinline__ unsigned packu(float v) {
    __nv_bfloat16 h, l;
    split1(v, h, l);
    return (unsigned)__bfloat16_as_ushort(h) | ((unsigned)__bfloat16_as_ushort(l) << 16);
}
__device__ __forceinline__ float unpacku(unsigned u) {
    return __bfloat162float(__ushort_as_bfloat16((unsigned short)(u & 0xffffu))) +
           __bfloat162float(__ushort_as_bfloat16((unsigned short)(u >> 16)));
}
__device__ __forceinline__ void ldmat4(unsigned (&r)[4], unsigned addr) {
    asm volatile("ldmatrix.sync.aligned.m8n8.x4.shared.b16 {%0,%1,%2,%3}, [%4];"
                 : "=r"(r[0]), "=r"(r[1]), "=r"(r[2]), "=r"(r[3]) : "r"(addr));
}
__device__ __forceinline__ void mma16816(float (&c)[4], const unsigned (&a)[4],
                                         unsigned b0, unsigned b1) {
    asm volatile(
        "mma.sync.aligned.m16n8k16.row.col.f32.bf16.bf16.f32 "
        "{%0,%1,%2,%3}, {%4,%5,%6,%7}, {%8,%9}, {%0,%1,%2,%3};"
        : "+f"(c[0]), "+f"(c[1]), "+f"(c[2]), "+f"(c[3])
        : "r"(a[0]), "r"(a[1]), "r"(a[2]), "r"(a[3]), "r"(b0), "r"(b1));
}
__device__ __forceinline__ void cp16(unsigned saddr, const void* gaddr, int srcsz) {
    asm volatile("cp.async.ca.shared.global [%0], [%1], 16, %2;"
                 :: "r"(saddr), "l"(gaddr), "r"(srcsz) : "memory");
}
#define CP_COMMIT() asm volatile("cp.async.commit_group;" ::: "memory")
#define CP_WAIT1()  asm volatile("cp.async.wait_group 1;" ::: "memory")

// ===========================================================================
// Resident-W GEMM for K=256: one 512-thread CTA, tile 128(M) x 256(N).
// W (hi+lo, 128KB) loaded once; B 3-stage pipelined (32KB/stage).
// 16 warps as 4m x 4n, warp tile 32x64. smem total 224KB (1 CTA/SM).
// EPI: 0 plain -> packed uint32 [b,t,o] stride OSTR
//      2 (resid+D+bias)*mask -> bf16 hi/lo planes
//      3 (D+bias)*mask -> fp32 [b,o,t]
// ===========================================================================
#define WREG     131072             // 8 chunks x (8KB hi + 8KB lo)
#define BSTG     32768              // 16KB hi + 16KB lo
#define SMEM_W   (WREG + 3 * BSTG)  // 229376

template <int EPI, int OROWS, int OSTR>
__global__ void __launch_bounds__(512, 1)
gemm_wres(const __nv_bfloat16* __restrict__ Whi, const __nv_bfloat16* __restrict__ Wlo,
          const __nv_bfloat16* __restrict__ Ahi, const __nv_bfloat16* __restrict__ Alo,
          const float* __restrict__ bias, const float* __restrict__ mask,
          const __nv_bfloat16* __restrict__ Rhi, const __nv_bfloat16* __restrict__ Rlo,
          __nv_bfloat16* __restrict__ Ohi, __nv_bfloat16* __restrict__ Olo,
          float* __restrict__ OF)
{
    extern __shared__ char smem[];
    const unsigned sb = smem_u32(smem);
    const int tid  = threadIdx.x;
    const int lane = tid & 31, wid = tid >> 5;
    const int bT = blockIdx.x * 256;
    const int bO = blockIdx.y * 128;
    const int b  = blockIdx.z;
    const int m0 = (wid & 3) * 32;
    const int n0 = (wid >> 2) * 64;

    constexpr bool GUARDA = (OROWS & 127) != 0;
    constexpr int KTOT = 256, NCH = 8;

    const __nv_bfloat16* Bh = Ahi + ((size_t)b * Tq + bT) * KTOT;
    const __nv_bfloat16* Bl = Alo + ((size_t)b * Tq + bT) * KTOT;

    // ldmatrix per-thread swizzled offsets (64B stride, chunk ^= (row>>1)&3)
    const int raA  = lane & 15;
    const int xorA = (raA >> 1) & 3;
    const int laA[2] = { raA * 64 + ((((lane >> 4)    ) ^ xorA) << 4),
                         raA * 64 + ((((lane >> 4) + 2) ^ xorA) << 4) };
    const int matv = lane >> 3;
    const int rbB  = (lane & 7) + ((matv >> 1) * 8);
    const int xorB = (rbB >> 1) & 3;
    const int lbB[2] = { rbB * 64 + ((((matv & 1)    ) ^ xorB) << 4),
                         rbB * 64 + ((((matv & 1) + 2) ^ xorB) << 4) };

    float acc[2][8][4];
#pragma unroll
    for (int i = 0; i < 2; i++)
#pragma unroll
        for (int j = 0; j < 8; j++)
#pragma unroll
            for (int l = 0; l < 4; l++) acc[i][j][l] = 0.f;

    // ---- B-chunk async issue (always commits one group) ----
    auto issueB = [&](int ch, int stg) {
        if (ch < NCH) {
            const unsigned st = sb + WREG + stg * BSTG;
            const int k0 = ch * 32;
#pragma unroll
            for (int i = 0; i < 4; i++) {
                const int idx = i * 512 + tid;      // 0..2047
                const int p = idx >> 10;            // plane (hi/lo)
                const int q = idx & 1023;
                const int r = q >> 2, c = q & 3;    // t-row 0..255, 16B col
                const unsigned soff = (unsigned)(p * 16384 + r * 64 + ((c ^ ((r >> 1) & 3)) << 4));
                const size_t boff = (size_t)r * KTOT + k0 + c * 8;
                cp16(st + soff, (p ? Bl : Bh) + boff, 16);
            }
        }
        CP_COMMIT();
    };

    // ---- prologue: W full tile (128KB) + B0 as group 0, then B1 ----
    {
#pragma unroll
        for (int it = 0; it < 16; it++) {
            const int idx = it * 512 + tid;         // 0..8191
            const int p  = idx >> 12;               // plane
            const int q  = idx & 4095;
            const int ch = q >> 9;
            const int r  = (q >> 2) & 127;
            const int c  = q & 3;
            const unsigned soff = (unsigned)(ch * 16384 + p * 8192 + r * 64 +
                                             ((c ^ ((r >> 1) & 3)) << 4));
            int asz = 16;
            size_t aoff = (size_t)(bO + r) * KTOT + ch * 32 + c * 8;
            if (GUARDA && (bO + r >= OROWS)) { asz = 0; aoff = 0; }
            cp16(sb + soff, (p ? Wlo : Whi) + aoff, asz);
        }
    }
    issueB(0, 0);          // group 0 (includes W)
    issueB(1, 1);          // group 1

    int cs = 0, is = 2;
#pragma unroll 1
    for (int ch = 0; ch < NCH; ch++) {
        CP_WAIT1();
        __syncthreads();
        issueB(ch + 2, is);
        is = (is == 2) ? 0 : is + 1;

        const unsigned Ah_ = sb + ch * 16384;       // resident W, chunk-indexed
        const unsigned Al_ = Ah_ + 8192;
        const unsigned Bh_ = sb + WREG + cs * BSTG;
        const unsigned Bl_ = Bh_ + 16384;
        cs = (cs == 2) ? 0 : cs + 1;

#pragma unroll
        for (int kk = 0; kk < 2; kk++) {
            unsigned ah[2][4], al[2][4];
            ldmat4(ah[0], Ah_ + (m0     ) * 64 + laA[kk]);
            ldmat4(ah[1], Ah_ + (m0 + 16) * 64 + laA[kk]);
            ldmat4(al[0], Al_ + (m0     ) * 64 + laA[kk]);
            ldmat4(al[1], Al_ + (m0 + 16) * 64 + laA[kk]);
#pragma unroll
            for (int nt2 = 0; nt2 < 4; nt2++) {
                unsigned bh[4], bl[4];
                ldmat4(bh, Bh_ + (n0 + nt2 * 16) * 64 + lbB[kk]);
                ldmat4(bl, Bl_ + (n0 + nt2 * 16) * 64 + lbB[kk]);
                mma16816(acc[0][nt2 * 2 + 0], ah[0], bh[0], bh[1]);
                mma16816(acc[0][nt2 * 2 + 1], ah[0], bh[2], bh[3]);
                mma16816(acc[1][nt2 * 2 + 0], ah[1], bh[0], bh[1]);
                mma16816(acc[1][nt2 * 2 + 1], ah[1], bh[2], bh[3]);
                mma16816(acc[0][nt2 * 2 + 0], ah[0], bl[0], bl[1]);
                mma16816(acc[0][nt2 * 2 + 1], ah[0], bl[2], bl[3]);
                mma16816(acc[1][nt2 * 2 + 0], ah[1], bl[0], bl[1]);
                mma16816(acc[1][nt2 * 2 + 1], ah[1], bl[2], bl[3]);
                mma16816(acc[0][nt2 * 2 + 0], al[0], bh[0], bh[1]);
                mma16816(acc[0][nt2 * 2 + 1], al[0], bh[2], bh[3]);
                mma16816(acc[1][nt2 * 2 + 0], al[1], bh[0], bh[1]);
                mma16816(acc[1][nt2 * 2 + 1], al[1], bh[2], bh[3]);
            }
        }
    }

    // ---- epilogue ----
    const int g = lane >> 2, tig = lane & 3;
#pragma unroll
    for (int mi = 0; mi < 2; mi++) {
#pragma unroll
        for (int pr = 0; pr < 2; pr++) {
            const int o = bO + m0 + mi * 16 + g + pr * 8;
            float bs = 0.f;
            if (EPI >= 1) bs = (!GUARDA || o < OROWS) ? bias[o] : 0.f;
#pragma unroll
            for (int nt = 0; nt < 8; nt++) {
                const int t = bT + n0 + nt * 8 + 2 * tig;
                float v0 = acc[mi][nt][pr * 2 + 0] + bs;
                float v1 = acc[mi][nt][pr * 2 + 1] + bs;
                if (EPI == 0) {
                    unsigned* Op = (unsigned*)Ohi;
                    const size_t i0 = ((size_t)b * Tq + t) * OSTR + o;
                    Op[i0]        = packu(v0);
                    Op[i0 + OSTR] = packu(v1);
                } else if (EPI == 3) {
                    if (!GUARDA || o < OROWS) {
                        const float mk0 = mask[(size_t)b * Tq + t];
                        const float mk1 = mask[(size_t)b * Tq + t + 1];
                        *(float2*)(OF + ((size_t)b * OROWS + o) * Tq + t) =
                            make_float2(v0 * mk0, v1 * mk1);
                    }
                } else {
                    const size_t i0 = ((size_t)b * Tq + t) * OSTR + o;
                    const float mk0 = mask[(size_t)b * Tq + t];
                    const float mk1 = mask[(size_t)b * Tq + t + 1];
                    float r0 = __bfloat162float(Rhi[i0]) + __bfloat162float(Rlo[i0]);
                    float r1 = __bfloat162float(Rhi[i0 + OSTR]) + __bfloat162float(Rlo[i0 + OSTR]);
                    v0 = (r0 + v0) * mk0;
                    v1 = (r1 + v1) * mk1;
                    __nv_bfloat16 h0, l0, h1, l1;
                    split1(v0, h0, l0);
                    split1(v1, h1, l1);
                    Ohi[i0] = h0; Olo[i0] = l0;
                    Ohi[i0 + OSTR] = h1; Olo[i0 + OSTR] = l1;
                }
            }
        }
    }
}

// ===========================================================================
// Streaming GEMM (K=1024 input layer only) — proven R7 path.
// Block 128x128, 256 threads, 3-stage cp.async.  EPI=1: +bias -> bf16 planes.
// ===========================================================================
#define TILE_P   8192
#define STAGE    32768
#define SMEM_S   98304

__global__ void __launch_bounds__(256, 2)
gemm_b0(const __nv_bfloat16* __restrict__ Whi, const __nv_bfloat16* __restrict__ Wlo,
        const __nv_bfloat16* __restrict__ Ahi, const __nv_bfloat16* __restrict__ Alo,
        const float* __restrict__ bias,
        __nv_bfloat16* __restrict__ Ohi, __nv_bfloat16* __restrict__ Olo)
{
    extern __shared__ char smem[];
    const unsigned sb = smem_u32(smem);
    const int tid  = threadIdx.x;
    const int lane = tid & 31, wid = tid >> 5;
    const int bT = blockIdx.x * 128;
    const int bO = blockIdx.y * 128;
    const int b  = blockIdx.z;
    const int m0 = (wid & 3) * 32;
    const int n0 = (wid >> 2) * 64;

    constexpr int KTOT = DINq, NCH = KTOT / 32;

    const __nv_bfloat16* Bh = Ahi + ((size_t)b * Tq + bT) * KTOT;
    const __nv_bfloat16* Bl = Alo + ((size_t)b * Tq + bT) * KTOT;

    const int raA  = lane & 15;
    const int xorA = (raA >> 1) & 3;
    const int laA[2] = { raA * 64 + ((((lane >> 4)    ) ^ xorA) << 4),
                         raA * 64 + ((((lane >> 4) + 2) ^ xorA) << 4) };
    const int matv = lane >> 3;
    const int rbB  = (lane & 7) + ((matv >> 1) * 8);
    const int xorB = (rbB >> 1) & 3;
    const int lbB[2] = { rbB * 64 + ((((matv & 1)    ) ^ xorB) << 4),
                         rbB * 64 + ((((matv & 1) + 2) ^ xorB) << 4) };

    float acc[2][8][4];
#pragma unroll
    for (int i = 0; i < 2; i++)
#pragma unroll
        for (int j = 0; j < 8; j++)
#pragma unroll
            for (int l = 0; l < 4; l++) acc[i][j][l] = 0.f;

    auto issue = [&](int ch, int stg) {
        if (ch < NCH) {
            const int k0 = ch * 32;
            const unsigned st = sb + stg * STAGE;
#pragma unroll
            for (int i = 0; i < 2; i++) {
                const int task = i * 256 + tid;
                const int row = task >> 2, c = task & 3;
                const unsigned soff = (unsigned)(row * 64 + ((c ^ ((row >> 1) & 3)) << 4));
                const size_t aoff = (size_t)(bO + row) * KTOT + k0 + c * 8;
                cp16(st + soff,              Whi + aoff, 16);
                cp16(st + TILE_P + soff,     Wlo + aoff, 16);
                const size_t boff = (size_t)row * KTOT + k0 + c * 8;
                cp16(st + 2 * TILE_P + soff, Bh + boff, 16);
                cp16(st + 3 * TILE_P + soff, Bl + boff, 16);
            }
        }
        CP_COMMIT();
    };

    issue(0, 0);
    issue(1, 1);

    int cs = 0, is = 2;
#pragma unroll 1
    for (int ch = 0; ch < NCH; ch++) {
        CP_WAIT1();
        __syncthreads();
        issue(ch + 2, is);
        is = (is == 2) ? 0 : is + 1;

        const unsigned Ah_ = sb + cs * STAGE;
        const unsigned Al_ = Ah_ + TILE_P;
        const unsigned Bh_ = Ah_ + 2 * TILE_P;
        const unsigned Bl_ = Ah_ + 3 * TILE_P;
        cs = (cs == 2) ? 0 : cs + 1;

#pragma unroll
        for (int kk = 0; kk < 2; kk++) {
            unsigned ah[2][4], al[2][4];
            ldmat4(ah[0], Ah_ + (m0     ) * 64 + laA[kk]);
            ldmat4(ah[1], Ah_ + (m0 + 16) * 64 + laA[kk]);
            ldmat4(al[0], Al_ + (m0     ) * 64 + laA[kk]);
            ldmat4(al[1], Al_ + (m0 + 16) * 64 + laA[kk]);
#pragma unroll
            for (int nt2 = 0; nt2 < 4; nt2++) {
                unsigned bh[4], bl[4];
                ldmat4(bh, Bh_ + (n0 + nt2 * 16) * 64 + lbB[kk]);
                ldmat4(bl, Bl_ + (n0 + nt2 * 16) * 64 + lbB[kk]);
                mma16816(acc[0][nt2 * 2 + 0], ah[0], bh[0], bh[1]);
                mma16816(acc[0][nt2 * 2 + 1], ah[0], bh[2], bh[3]);
                mma16816(acc[1][nt2 * 2 + 0], ah[1], bh[0], bh[1]);
                mma16816(acc[1][nt2 * 2 + 1], ah[1], bh[2], bh[3]);
                mma16816(acc[0][nt2 * 2 + 0], ah[0], bl[0], bl[1]);
                mma16816(acc[0][nt2 * 2 + 1], ah[0], bl[2], bl[3]);
                mma16816(acc[1][nt2 * 2 + 0], ah[1], bl[0], bl[1]);
                mma16816(acc[1][nt2 * 2 + 1], ah[1], bl[2], bl[3]);
                mma16816(acc[0][nt2 * 2 + 0], al[0], bh[0], bh[1]);
                mma16816(acc[0][nt2 * 2 + 1], al[0], bh[2], bh[3]);
                mma16816(acc[1][nt2 * 2 + 0], al[1], bh[0], bh[1]);
                mma16816(acc[1][nt2 * 2 + 1], al[1], bh[2], bh[3]);
            }
        }
    }

    const int g = lane >> 2, tig = lane & 3;
#pragma unroll
    for (int mi = 0; mi < 2; mi++) {
#pragma unroll
        for (int pr = 0; pr < 2; pr++) {
            const int o = bO + m0 + mi * 16 + g + pr * 8;
            const float bs = bias[o];
#pragma unroll
            for (int nt = 0; nt < 8; nt++) {
                const int t = bT + n0 + nt * 8 + 2 * tig;
                const size_t i0 = ((size_t)b * Tq + t) * DMq + o;
                __nv_bfloat16 h0, l0, h1, l1;
                split1(acc[mi][nt][pr * 2 + 0] + bs, h0, l0);
                split1(acc[mi][nt][pr * 2 + 1] + bs, h1, l1);
                Ohi[i0] = h0; Olo[i0] = l0;
                Ohi[i0 + DMq] = h1; Olo[i0 + DMq] = l1;
            }
        }
    }
}

// ---------------------------------------------------------------------------
// x transpose + split: [B, DIN, T] fp32 -> [B, T, DIN] bf16 hi/lo
// ---------------------------------------------------------------------------
__global__ __launch_bounds__(256)
void xpose_kernel(const float* __restrict__ x,
                  __nv_bfloat16* __restrict__ xh, __nv_bfloat16* __restrict__ xl)
{
    __shared__ float s[32][33];
    const int t0 = blockIdx.x * 32, i0 = blockIdx.y * 32, b = blockIdx.z;
    const int tx = threadIdx.x & 31, ty = threadIdx.x >> 5;
    const float* xb = x + (size_t)b * DINq * Tq;
#pragma unroll
    for (int kk = 0; kk < 4; kk++)
        s[ty + 8 * kk][tx] = xb[(size_t)(i0 + ty + 8 * kk) * Tq + t0 + tx];
    __syncthreads();
#pragma unroll
    for (int kk = 0; kk < 4; kk++) {
        const float v = s[tx][ty + 8 * kk];
        const size_t idx = ((size_t)b * Tq + t0 + ty + 8 * kk) * DINq + i0 + tx;
        __nv_bfloat16 h, l;
        split1(v, h, l);
        xh[idx] = h; xl[idx] = l;
    }
}

// ---------------------------------------------------------------------------
// Weight split
// ---------------------------------------------------------------------------
struct WPtrs { const float* p[22]; };

__global__ __launch_bounds__(256)
void convw_kernel(WPtrs wp, __nv_bfloat16* __restrict__ wh, __nv_bfloat16* __restrict__ wl)
{
    const int idx = blockIdx.x * 256 + threadIdx.x;
    int off = 0;
#pragma unroll
    for (int m = 0; m < 22; m++) {
        const int sz = (m == 0) ? 262144 : ((m == 21) ? NCq * DMq : 65536);
        if (idx < off + sz) {
            __nv_bfloat16 h, l;
            split1(wp.p[m][idx - off], h, l);
            wh[idx] = h; wl[idx] = l;
            return;
        }
        off += sz;
    }
}

// ---------------------------------------------------------------------------
// Dilated 3-tap softmax attention + ReLU, reading packed qkv [B,T,768]
// ---------------------------------------------------------------------------
__device__ __forceinline__ void load4p(const unsigned* __restrict__ p, size_t e, float (&o)[4])
{
    const uint4 u = *(const uint4*)(p + e);
    o[0] = unpacku(u.x);
    o[1] = unpacku(u.y);
    o[2] = unpacku(u.z);
    o[3] = unpacku(u.w);
}

__device__ __forceinline__ float attn1(float q, float k0, float k1, float k2,
                                       float v0, float v1, float v2)
{
    const float s0 = q * k0, s1 = q * k1, s2 = q * k2;
    const float mx = fmaxf(s0, fmaxf(s1, s2));
    const float e0 = __expf(s0 - mx), e1 = __expf(s1 - mx), e2 = __expf(s2 - mx);
    return fmaxf((e0 * v0 + e1 * v1 + e2 * v2) / (e0 + e1 + e2), 0.f);
}

__global__ __launch_bounds__(256)
void attn_kernel(const unsigned* __restrict__ qkvp,
                 __nv_bfloat16* __restrict__ hh, __nv_bfloat16* __restrict__ hl, int d)
{
    const size_t gid = (size_t)blockIdx.x * 256 + threadIdx.x;
    const int c4 = (int)(gid & 63);
    const int t  = (int)((gid >> 6) & (Tq - 1));
    const int b  = (int)(gid >> 18);
    const size_t rq = ((size_t)b * Tq + t) * 768 + c4 * 4;
    const long long off = (long long)d * 768;

    float q[4], k1[4], v1[4];
    load4p(qkvp, rq,       q);
    load4p(qkvp, rq + 256, k1);
    load4p(qkvp, rq + 512, v1);
    float k0[4] = {0, 0, 0, 0}, v0[4] = {0, 0, 0, 0};
    float k2[4] = {0, 0, 0, 0}, v2[4] = {0, 0, 0, 0};
    if (t - d >= 0) { load4p(qkvp, rq + 256 - off, k0); load4p(qkvp, rq + 512 - off, v0); }
    if (t + d < Tq) { load4p(qkvp, rq + 256 + off, k2); load4p(qkvp, rq + 512 + off, v2); }

    const size_t e = ((size_t)b * Tq + t) * DMq + c4 * 4;
    __nv_bfloat16 rh[4], rl[4];
#pragma unroll
    for (int c = 0; c < 4; c++) {
        const float r = attn1(q[c], k0[c], k1[c], k2[c], v0[c], v1[c], v2[c]);
        split1(r, rh[c], rl[c]);
    }
    *(__nv_bfloat162*)(hh + e)     = __nv_bfloat162(rh[0], rh[1]);
    *(__nv_bfloat162*)(hh + e + 2) = __nv_bfloat162(rh[2], rh[3]);
    *(__nv_bfloat162*)(hl + e)     = __nv_bfloat162(rl[0], rl[1]);
    *(__nv_bfloat162*)(hl + e + 2) = __nv_bfloat162(rl[2], rl[3]);
}

// ---------------------------------------------------------------------------
// Launch
// ---------------------------------------------------------------------------
extern "C" void kernel_launch(void* const* d_in, const int* in_sizes, int n_in,
                              void* d_out, int out_size)
{
    const float* x    = (const float*)d_in[0];
    const float* mask = (const float*)d_in[1];
    const float* b0b  = (const float*)d_in[3];
    const float* b6b  = (const float*)d_in[30];

    __nv_bfloat16 *xh, *xl, *oh, *ol, *hh, *hl, *wh, *wl;
    unsigned *qkvp;
    cudaGetSymbolAddress((void**)&xh, g_xh);      cudaGetSymbolAddress((void**)&xl, g_xl);
    cudaGetSymbolAddress((void**)&oh, g_oh);      cudaGetSymbolAddress((void**)&ol, g_ol);
    cudaGetSymbolAddress((void**)&qkvp, g_qkvp);
    cudaGetSymbolAddress((void**)&hh, g_hh);      cudaGetSymbolAddress((void**)&hl, g_hl);
    cudaGetSymbolAddress((void**)&wh, g_wh);      cudaGetSymbolAddress((void**)&wl, g_wl);

    cudaFuncSetAttribute(gemm_b0, cudaFuncAttributeMaxDynamicSharedMemorySize, SMEM_S);
    cudaFuncSetAttribute(gemm_wres<0, 3 * DMq, 3 * DMq>, cudaFuncAttributeMaxDynamicSharedMemorySize, SMEM_W);
    cudaFuncSetAttribute(gemm_wres<2, DMq, DMq>,         cudaFuncAttributeMaxDynamicSharedMemorySize, SMEM_W);
    cudaFuncSetAttribute(gemm_wres<3, NCq, DMq>,         cudaFuncAttributeMaxDynamicSharedMemorySize, SMEM_W);

    // split weights
    WPtrs wp;
    wp.p[0] = (const float*)d_in[2];
    for (int l = 0; l < 5; l++) {
        wp.p[1 + 4 * l + 0] = (const float*)d_in[4 + 5 * l + 0];
        wp.p[1 + 4 * l + 1] = (const float*)d_in[4 + 5 * l + 1];
        wp.p[1 + 4 * l + 2] = (const float*)d_in[4 + 5 * l + 2];
        wp.p[1 + 4 * l + 3] = (const float*)d_in[4 + 5 * l + 3];
    }
    wp.p[21] = (const float*)d_in[29];
    convw_kernel<<<W_TOTAL / 256, 256>>>(wp, wh, wl);

    // transpose + split input
    xpose_kernel<<<dim3(Tq / 32, DINq / 32, Bq), 256>>>(x, xh, xl);

    const dim3 g_b0 (Tq / 128, DMq / 128, Bq);             // (32, 2, 8)
    const dim3 g_qkv(Tq / 256, 3 * DMq / 128, Bq);         // (16, 6, 8)
    const dim3 g_dm (Tq / 256, DMq / 128, Bq);             // (16, 2, 8)
    const dim3 g_nc (Tq / 256, (NCq + 127) / 128, Bq);     // (16, 2, 8)
    const int  g_at = (Bq * Tq * 64) / 256;                // 8192

    // input GEMM: out = b0w @ xt + b0b  (streaming, K=1024)
    gemm_b0<<<g_b0, 256, SMEM_S>>>(wh + W_B0, wl + W_B0, xh, xl, b0b, oh, ol);

    const int dils[5] = {1, 2, 4, 8, 16};
    for (int l = 0; l < 5; l++) {
        const float* bb = (const float*)d_in[4 + 5 * l + 4];
        const int wqkv = W_L0 + l * W_PERL;          // wq|wk|wv stacked (768x256)
        const int bw   = wqkv + 3 * 65536;

        // fused QKV GEMM -> packed qkv [b,t,768]  (resident W)
        gemm_wres<0, 3 * DMq, 3 * DMq><<<g_qkv, 512, SMEM_W>>>(
            wh + wqkv, wl + wqkv, oh, ol, nullptr, nullptr, nullptr, nullptr,
            (__nv_bfloat16*)qkvp, nullptr, nullptr);

        attn_kernel<<<g_at, 256>>>(qkvp, hh, hl, dils[l]);

        // out = (out + bw@h + bb) * mask  (resident W)
        gemm_wres<2, DMq, DMq><<<g_dm, 512, SMEM_W>>>(
            wh + bw, wl + bw, hh, hl, bb, mask, oh, ol, oh, ol, nullptr);
    }

    // final: (b6w @ out + b6b) * mask -> fp32 [B, NC, T]  (resident W)
    gemm_wres<3, NCq, DMq><<<g_nc, 512, SMEM_W>>>(
        wh + W_B6, wl + W_B6, oh, ol, b6b, mask, nullptr, nullptr, nullptr, nullptr, (float*)d_out);
}

// round 9
// speedup vs baseline: 1.2608x; 1.2608x over previous
#include <cuda_runtime.h>
#include <cuda_bf16.h>

#define Bq   8
#define Tq   4096
#define DINq 1024
#define DMq  256
#define NCq  157

// ---------------------------------------------------------------------------
// Scratch: activations in [B, T, C] (K-major for MMA B operand)
// GEMM inputs (out, h, xt): separate bf16 hi/lo planes (pre-split for cp.async)
// qkv (GEMM output -> attention only): packed uint32 = hi | lo<<16
// value = float(hi) + float(lo)  (error ~2^-18 relative)
// ---------------------------------------------------------------------------
__device__ __nv_bfloat16 g_xh  [Bq * Tq * DINq];
__device__ __nv_bfloat16 g_xl  [Bq * Tq * DINq];
__device__ __nv_bfloat16 g_oh  [Bq * Tq * DMq];
__device__ __nv_bfloat16 g_ol  [Bq * Tq * DMq];
__device__ unsigned      g_qkvp[Bq * Tq * 3 * DMq];
__device__ __nv_bfloat16 g_hh  [Bq * Tq * DMq];
__device__ __nv_bfloat16 g_hl  [Bq * Tq * DMq];

// Weights split hi/lo, packed: b0w(256x1024), per layer wq|wk|wv|bw, b6w(157x256)
#define W_B0    0
#define W_L0    262144
#define W_PERL  (4 * 65536)
#define W_B6    (262144 + 5 * W_PERL)
#define W_TOTAL (W_B6 + NCq * DMq)
__device__ __nv_bfloat16 g_wh[W_TOTAL];
__device__ __nv_bfloat16 g_wl[W_TOTAL];

// ---------------------------------------------------------------------------
// Helpers
// ---------------------------------------------------------------------------
__device__ __forceinline__ unsigned smem_u32(const void* p) {
    unsigned a;
    asm("{ .reg .u64 t; cvta.to.shared.u64 t, %1; cvt.u32.u64 %0, t; }" : "=r"(a) : "l"(p));
    return a;
}
__device__ __forceinline__ void split1(float v, __nv_bfloat16& h, __nv_bfloat16& l) {
    h = __float2bfloat16_rn(v);
    l = __float2bfloat16_rn(v - __bfloat162float(h));
}
__device__ __forceinline__ unsigned packu(float v) {
    __nv_bfloat16 h, l;
    split1(v, h, l);
    return (unsigned)__bfloat16_as_ushort(h) | ((unsigned)__bfloat16_as_ushort(l) << 16);
}
__device__ __forceinline__ float unpacku(unsigned u) {
    return __bfloat162float(__ushort_as_bfloat16((unsigned short)(u & 0xffffu))) +
           __bfloat162float(__ushort_as_bfloat16((unsigned short)(u >> 16)));
}
__device__ __forceinline__ void ldmat4(unsigned (&r)[4], unsigned addr) {
    asm volatile("ldmatrix.sync.aligned.m8n8.x4.shared.b16 {%0,%1,%2,%3}, [%4];"
                 : "=r"(r[0]), "=r"(r[1]), "=r"(r[2]), "=r"(r[3]) : "r"(addr));
}
__device__ __forceinline__ void mma16816(float (&c)[4], const unsigned (&a)[4],
                                         unsigned b0, unsigned b1) {
    asm volatile(
        "mma.sync.aligned.m16n8k16.row.col.f32.bf16.bf16.f32 "
        "{%0,%1,%2,%3}, {%4,%5,%6,%7}, {%8,%9}, {%0,%1,%2,%3};"
        : "+f"(c[0]), "+f"(c[1]), "+f"(c[2]), "+f"(c[3])
        : "r"(a[0]), "r"(a[1]), "r"(a[2]), "r"(a[3]), "r"(b0), "r"(b1));
}
// L1-bypass async copy: tiles have zero L1 reuse, keep L1 for LDSM traffic.
__device__ __forceinline__ void cp16(unsigned saddr, const void* gaddr, int srcsz) {
    asm volatile("cp.async.cg.shared.global [%0], [%1], 16, %2;"
                 :: "r"(saddr), "l"(gaddr), "r"(srcsz) : "memory");
}
#define CP_COMMIT() asm volatile("cp.async.commit_group;" ::: "memory")
#define CP_WAIT1()  asm volatile("cp.async.wait_group 1;" ::: "memory")

// ---------------------------------------------------------------------------
// GEMM: D[o,t] = sum_i W[o,i] * Act[b,t,i]   (split-bf16 x3, mma.sync)
// Block 128(M=o) x 128(N=t), K-chunk 32, 256 threads (8 warps, 4m x 2n),
// warp tile 32x64. cp.async 3-stage pipeline, 64B stride + XOR swizzle.
// EPI: 0 plain -> packed uint32 [b,t,o] stride OSTR
//      1 +bias -> bf16 hi/lo
//      2 (resid+D+bias)*mask -> bf16 hi/lo
//      3 (D+bias)*mask -> fp32 [b,o,t]
// ---------------------------------------------------------------------------
#define TILE_P   8192               // one 128x32 bf16 part (64B stride)
#define STAGE    32768              // A.hi A.lo B.hi B.lo
#define SMEM_TOT 98304              // 3 stages

template <int EPI, int KTOT, int OROWS, int OSTR>
__global__ void __launch_bounds__(256, 2)
gemm_mma(const __nv_bfloat16* __restrict__ Whi, const __nv_bfloat16* __restrict__ Wlo,
         const __nv_bfloat16* __restrict__ Ahi, const __nv_bfloat16* __restrict__ Alo,
         const float* __restrict__ bias, const float* __restrict__ mask,
         const __nv_bfloat16* __restrict__ Rhi, const __nv_bfloat16* __restrict__ Rlo,
         __nv_bfloat16* __restrict__ Ohi, __nv_bfloat16* __restrict__ Olo,
         float* __restrict__ OF)
{
    extern __shared__ char smem[];
    const unsigned sb = smem_u32(smem);
    const int tid  = threadIdx.x;
    const int lane = tid & 31, wid = tid >> 5;
    const int bT = blockIdx.x * 128;
    const int bO = blockIdx.y * 128;
    const int b  = blockIdx.z;
    const int m0 = (wid & 3) * 32;
    const int n0 = (wid >> 2) * 64;

    constexpr bool GUARDA = (OROWS & 127) != 0;
    constexpr int NCH = KTOT / 32;

    const __nv_bfloat16* Bh = Ahi + ((size_t)b * Tq + bT) * KTOT;
    const __nv_bfloat16* Bl = Alo + ((size_t)b * Tq + bT) * KTOT;

    // ldmatrix per-thread swizzled offsets (64B stride, chunk ^= (row>>1)&3)
    const int raA  = lane & 15;
    const int xorA = (raA >> 1) & 3;
    const int laA[2] = { raA * 64 + ((((lane >> 4)    ) ^ xorA) << 4),
                         raA * 64 + ((((lane >> 4) + 2) ^ xorA) << 4) };
    const int matv = lane >> 3;
    const int rbB  = (lane & 7) + ((matv >> 1) * 8);
    const int xorB = (rbB >> 1) & 3;
    const int lbB[2] = { rbB * 64 + ((((matv & 1)    ) ^ xorB) << 4),
                         rbB * 64 + ((((matv & 1) + 2) ^ xorB) << 4) };

    float acc[2][8][4];
#pragma unroll
    for (int i = 0; i < 2; i++)
#pragma unroll
        for (int j = 0; j < 8; j++)
#pragma unroll
            for (int l = 0; l < 4; l++) acc[i][j][l] = 0.f;

    // ---- async tile issue (always commits exactly one group) ----
    auto issue = [&](int ch, int stg) {
        if (ch < NCH) {
            const int k0 = ch * 32;
            const unsigned st = sb + stg * STAGE;
#pragma unroll
            for (int i = 0; i < 2; i++) {
                const int task = i * 256 + tid;
                const int row = task >> 2, c = task & 3;
                const unsigned soff = (unsigned)(row * 64 + ((c ^ ((row >> 1) & 3)) << 4));
                int asz = 16;
                size_t aoff = (size_t)(bO + row) * KTOT + k0 + c * 8;
                if (GUARDA && (bO + row >= OROWS)) { asz = 0; aoff = 0; }
                cp16(st + soff,              Whi + aoff, asz);
                cp16(st + TILE_P + soff,     Wlo + aoff, asz);
                const size_t boff = (size_t)row * KTOT + k0 + c * 8;
                cp16(st + 2 * TILE_P + soff, Bh + boff, 16);
                cp16(st + 3 * TILE_P + soff, Bl + boff, 16);
            }
        }
        CP_COMMIT();
    };

    issue(0, 0);
    issue(1, 1);

    int cs = 0, is = 2;
#pragma unroll 1
    for (int ch = 0; ch < NCH; ch++) {
        CP_WAIT1();
        __syncthreads();
        issue(ch + 2, is);
        is = (is == 2) ? 0 : is + 1;

        const unsigned Ah_ = sb + cs * STAGE;
        const unsigned Al_ = Ah_ + TILE_P;
        const unsigned Bh_ = Ah_ + 2 * TILE_P;
        const unsigned Bl_ = Ah_ + 3 * TILE_P;
        cs = (cs == 2) ? 0 : cs + 1;

#pragma unroll
        for (int kk = 0; kk < 2; kk++) {
            unsigned ah[2][4], al[2][4];
            ldmat4(ah[0], Ah_ + (m0     ) * 64 + laA[kk]);
            ldmat4(ah[1], Ah_ + (m0 + 16) * 64 + laA[kk]);
            ldmat4(al[0], Al_ + (m0     ) * 64 + laA[kk]);
            ldmat4(al[1], Al_ + (m0 + 16) * 64 + laA[kk]);
#pragma unroll
            for (int nt2 = 0; nt2 < 4; nt2++) {
                unsigned bh[4], bl[4];
                ldmat4(bh, Bh_ + (n0 + nt2 * 16) * 64 + lbB[kk]);
                ldmat4(bl, Bl_ + (n0 + nt2 * 16) * 64 + lbB[kk]);
                mma16816(acc[0][nt2 * 2 + 0], ah[0], bh[0], bh[1]);
                mma16816(acc[0][nt2 * 2 + 1], ah[0], bh[2], bh[3]);
                mma16816(acc[1][nt2 * 2 + 0], ah[1], bh[0], bh[1]);
                mma16816(acc[1][nt2 * 2 + 1], ah[1], bh[2], bh[3]);
                mma16816(acc[0][nt2 * 2 + 0], ah[0], bl[0], bl[1]);
                mma16816(acc[0][nt2 * 2 + 1], ah[0], bl[2], bl[3]);
                mma16816(acc[1][nt2 * 2 + 0], ah[1], bl[0], bl[1]);
                mma16816(acc[1][nt2 * 2 + 1], ah[1], bl[2], bl[3]);
                mma16816(acc[0][nt2 * 2 + 0], al[0], bh[0], bh[1]);
                mma16816(acc[0][nt2 * 2 + 1], al[0], bh[2], bh[3]);
                mma16816(acc[1][nt2 * 2 + 0], al[1], bh[0], bh[1]);
                mma16816(acc[1][nt2 * 2 + 1], al[1], bh[2], bh[3]);
            }
        }
    }

    // ---- epilogue ----
    const int g = lane >> 2, tig = lane & 3;
#pragma unroll
    for (int mi = 0; mi < 2; mi++) {
#pragma unroll
        for (int pr = 0; pr < 2; pr++) {
            const int o = bO + m0 + mi * 16 + g + pr * 8;
            float bs = 0.f;
            if (EPI >= 1) bs = (!GUARDA || o < OROWS) ? bias[o] : 0.f;
#pragma unroll
            for (int nt = 0; nt < 8; nt++) {
                const int t = bT + n0 + nt * 8 + 2 * tig;
                float v0 = acc[mi][nt][pr * 2 + 0] + bs;
                float v1 = acc[mi][nt][pr * 2 + 1] + bs;
                if (EPI == 0) {
                    // packed uint32 output (qkv): coalesced 32B segments
                    unsigned* Op = (unsigned*)Ohi;
                    const size_t i0 = ((size_t)b * Tq + t) * OSTR + o;
                    Op[i0]        = packu(v0);
                    Op[i0 + OSTR] = packu(v1);
                } else if (EPI == 3) {
                    if (!GUARDA || o < OROWS) {
                        const float mk0 = mask[(size_t)b * Tq + t];
                        const float mk1 = mask[(size_t)b * Tq + t + 1];
                        *(float2*)(OF + ((size_t)b * OROWS + o) * Tq + t) =
                            make_float2(v0 * mk0, v1 * mk1);
                    }
                } else {
                    const size_t i0 = ((size_t)b * Tq + t) * OSTR + o;
                    if (EPI == 2) {
                        const float mk0 = mask[(size_t)b * Tq + t];
                        const float mk1 = mask[(size_t)b * Tq + t + 1];
                        float r0 = __bfloat162float(Rhi[i0]) + __bfloat162float(Rlo[i0]);
                        float r1 = __bfloat162float(Rhi[i0 + OSTR]) + __bfloat162float(Rlo[i0 + OSTR]);
                        v0 = (r0 + v0) * mk0;
                        v1 = (r1 + v1) * mk1;
                    }
                    __nv_bfloat16 h0, l0, h1, l1;
                    split1(v0, h0, l0);
                    split1(v1, h1, l1);
                    Ohi[i0] = h0; Olo[i0] = l0;
                    Ohi[i0 + OSTR] = h1; Olo[i0 + OSTR] = l1;
                }
            }
        }
    }
}

// ---------------------------------------------------------------------------
// x transpose + split: [B, DIN, T] fp32 -> [B, T, DIN] bf16 hi/lo
// ---------------------------------------------------------------------------
__global__ __launch_bounds__(256)
void xpose_kernel(const float* __restrict__ x,
                  __nv_bfloat16* __restrict__ xh, __nv_bfloat16* __restrict__ xl)
{
    __shared__ float s[32][33];
    const int t0 = blockIdx.x * 32, i0 = blockIdx.y * 32, b = blockIdx.z;
    const int tx = threadIdx.x & 31, ty = threadIdx.x >> 5;
    const float* xb = x + (size_t)b * DINq * Tq;
#pragma unroll
    for (int kk = 0; kk < 4; kk++)
        s[ty + 8 * kk][tx] = xb[(size_t)(i0 + ty + 8 * kk) * Tq + t0 + tx];
    __syncthreads();
#pragma unroll
    for (int kk = 0; kk < 4; kk++) {
        const float v = s[tx][ty + 8 * kk];
        const size_t idx = ((size_t)b * Tq + t0 + ty + 8 * kk) * DINq + i0 + tx;
        __nv_bfloat16 h, l;
        split1(v, h, l);
        xh[idx] = h; xl[idx] = l;
    }
}

// ---------------------------------------------------------------------------
// Weight split
// ---------------------------------------------------------------------------
struct WPtrs { const float* p[22]; };

__global__ __launch_bounds__(256)
void convw_kernel(WPtrs wp, __nv_bfloat16* __restrict__ wh, __nv_bfloat16* __restrict__ wl)
{
    const int idx = blockIdx.x * 256 + threadIdx.x;
    int off = 0;
#pragma unroll
    for (int m = 0; m < 22; m++) {
        const int sz = (m == 0) ? 262144 : ((m == 21) ? NCq * DMq : 65536);
        if (idx < off + sz) {
            __nv_bfloat16 h, l;
            split1(wp.p[m][idx - off], h, l);
            wh[idx] = h; wl[idx] = l;
            return;
        }
        off += sz;
    }
}

// ---------------------------------------------------------------------------
// Dilated 3-tap softmax attention + ReLU, reading packed qkv [B,T,768]
// ---------------------------------------------------------------------------
__device__ __forceinline__ void load4p(const unsigned* __restrict__ p, size_t e, float (&o)[4])
{
    const uint4 u = *(const uint4*)(p + e);
    o[0] = unpacku(u.x);
    o[1] = unpacku(u.y);
    o[2] = unpacku(u.z);
    o[3] = unpacku(u.w);
}

__device__ __forceinline__ float attn1(float q, float k0, float k1, float k2,
                                       float v0, float v1, float v2)
{
    const float s0 = q * k0, s1 = q * k1, s2 = q * k2;
    const float mx = fmaxf(s0, fmaxf(s1, s2));
    const float e0 = __expf(s0 - mx), e1 = __expf(s1 - mx), e2 = __expf(s2 - mx);
    return fmaxf((e0 * v0 + e1 * v1 + e2 * v2) / (e0 + e1 + e2), 0.f);
}

__global__ __launch_bounds__(256)
void attn_kernel(const unsigned* __restrict__ qkvp,
                 __nv_bfloat16* __restrict__ hh, __nv_bfloat16* __restrict__ hl, int d)
{
    const size_t gid = (size_t)blockIdx.x * 256 + threadIdx.x;
    const int c4 = (int)(gid & 63);
    const int t  = (int)((gid >> 6) & (Tq - 1));
    const int b  = (int)(gid >> 18);
    const size_t rq = ((size_t)b * Tq + t) * 768 + c4 * 4;
    const long long off = (long long)d * 768;

    float q[4], k1[4], v1[4];
    load4p(qkvp, rq,       q);
    load4p(qkvp, rq + 256, k1);
    load4p(qkvp, rq + 512, v1);
    float k0[4] = {0, 0, 0, 0}, v0[4] = {0, 0, 0, 0};
    float k2[4] = {0, 0, 0, 0}, v2[4] = {0, 0, 0, 0};
    if (t - d >= 0) { load4p(qkvp, rq + 256 - off, k0); load4p(qkvp, rq + 512 - off, v0); }
    if (t + d < Tq) { load4p(qkvp, rq + 256 + off, k2); load4p(qkvp, rq + 512 + off, v2); }

    const size_t e = ((size_t)b * Tq + t) * DMq + c4 * 4;
    __nv_bfloat16 rh[4], rl[4];
#pragma unroll
    for (int c = 0; c < 4; c++) {
        const float r = attn1(q[c], k0[c], k1[c], k2[c], v0[c], v1[c], v2[c]);
        split1(r, rh[c], rl[c]);
    }
    *(__nv_bfloat162*)(hh + e)     = __nv_bfloat162(rh[0], rh[1]);
    *(__nv_bfloat162*)(hh + e + 2) = __nv_bfloat162(rh[2], rh[3]);
    *(__nv_bfloat162*)(hl + e)     = __nv_bfloat162(rl[0], rl[1]);
    *(__nv_bfloat162*)(hl + e + 2) = __nv_bfloat162(rl[2], rl[3]);
}

// ---------------------------------------------------------------------------
// Launch
// ---------------------------------------------------------------------------
extern "C" void kernel_launch(void* const* d_in, const int* in_sizes, int n_in,
                              void* d_out, int out_size)
{
    const float* x    = (const float*)d_in[0];
    const float* mask = (const float*)d_in[1];
    const float* b0b  = (const float*)d_in[3];
    const float* b6b  = (const float*)d_in[30];

    __nv_bfloat16 *xh, *xl, *oh, *ol, *hh, *hl, *wh, *wl;
    unsigned *qkvp;
    cudaGetSymbolAddress((void**)&xh, g_xh);      cudaGetSymbolAddress((void**)&xl, g_xl);
    cudaGetSymbolAddress((void**)&oh, g_oh);      cudaGetSymbolAddress((void**)&ol, g_ol);
    cudaGetSymbolAddress((void**)&qkvp, g_qkvp);
    cudaGetSymbolAddress((void**)&hh, g_hh);      cudaGetSymbolAddress((void**)&hl, g_hl);
    cudaGetSymbolAddress((void**)&wh, g_wh);      cudaGetSymbolAddress((void**)&wl, g_wl);

    cudaFuncSetAttribute(gemm_mma<1, DINq, DMq, DMq>,        cudaFuncAttributeMaxDynamicSharedMemorySize, SMEM_TOT);
    cudaFuncSetAttribute(gemm_mma<0, DMq, 3 * DMq, 3 * DMq>, cudaFuncAttributeMaxDynamicSharedMemorySize, SMEM_TOT);
    cudaFuncSetAttribute(gemm_mma<2, DMq, DMq, DMq>,         cudaFuncAttributeMaxDynamicSharedMemorySize, SMEM_TOT);
    cudaFuncSetAttribute(gemm_mma<3, DMq, NCq, DMq>,         cudaFuncAttributeMaxDynamicSharedMemorySize, SMEM_TOT);

    // split weights
    WPtrs wp;
    wp.p[0] = (const float*)d_in[2];
    for (int l = 0; l < 5; l++) {
        wp.p[1 + 4 * l + 0] = (const float*)d_in[4 + 5 * l + 0];
        wp.p[1 + 4 * l + 1] = (const float*)d_in[4 + 5 * l + 1];
        wp.p[1 + 4 * l + 2] = (const float*)d_in[4 + 5 * l + 2];
        wp.p[1 + 4 * l + 3] = (const float*)d_in[4 + 5 * l + 3];
    }
    wp.p[21] = (const float*)d_in[29];
    convw_kernel<<<W_TOTAL / 256, 256>>>(wp, wh, wl);

    // transpose + split input
    xpose_kernel<<<dim3(Tq / 32, DINq / 32, Bq), 256>>>(x, xh, xl);

    const dim3 thr(256);
    const dim3 g_dm (Tq / 128, DMq / 128, Bq);             // (32, 2, 8)
    const dim3 g_qkv(Tq / 128, 3 * DMq / 128, Bq);         // (32, 6, 8)
    const dim3 g_nc (Tq / 128, (NCq + 127) / 128, Bq);     // (32, 2, 8)
    const int  g_at = (Bq * Tq * 64) / 256;                // 8192

    // input GEMM: out = b0w @ xt + b0b
    gemm_mma<1, DINq, DMq, DMq><<<g_dm, thr, SMEM_TOT>>>(
        wh + W_B0, wl + W_B0, xh, xl, b0b, nullptr, nullptr, nullptr, oh, ol, nullptr);

    const int dils[5] = {1, 2, 4, 8, 16};
    for (int l = 0; l < 5; l++) {
        const float* bb = (const float*)d_in[4 + 5 * l + 4];
        const int wqkv = W_L0 + l * W_PERL;          // wq|wk|wv stacked (768x256)
        const int bw   = wqkv + 3 * 65536;

        // fused QKV GEMM -> packed qkv [b,t,768]
        gemm_mma<0, DMq, 3 * DMq, 3 * DMq><<<g_qkv, thr, SMEM_TOT>>>(
            wh + wqkv, wl + wqkv, oh, ol, nullptr, nullptr, nullptr, nullptr,
            (__nv_bfloat16*)qkvp, nullptr, nullptr);

        attn_kernel<<<g_at, thr>>>(qkvp, hh, hl, dils[l]);

        // out = (out + bw@h + bb) * mask
        gemm_mma<2, DMq, DMq, DMq><<<g_dm, thr, SMEM_TOT>>>(
            wh + bw, wl + bw, hh, hl, bb, mask, oh, ol, oh, ol, nullptr);
    }

    // final: (b6w @ out + b6b) * mask -> fp32 [B, NC, T]
    gemm_mma<3, DMq, NCq, DMq><<<g_nc, thr, SMEM_TOT>>>(
        wh + W_B6, wl + W_B6, oh, ol, b6b, mask, nullptr, nullptr, nullptr, nullptr, (float*)d_out);
}

// round 10
// speedup vs baseline: 1.4791x; 1.1731x over previous
#include <cuda_runtime.h>
#include <cuda_bf16.h>

#define Bq   8
#define Tq   4096
#define DINq 1024
#define DMq  256
#define NCq  157

// ---------------------------------------------------------------------------
// Scratch: activations in [B, T, C] (K-major for MMA B operand)
// GEMM inputs (out, h, xt): separate bf16 hi/lo planes (pre-split for cp.async)
// qkv (GEMM output -> attention only): packed uint32 = hi | lo<<16
// ---------------------------------------------------------------------------
__device__ __nv_bfloat16 g_xh  [Bq * Tq * DINq];
__device__ __nv_bfloat16 g_xl  [Bq * Tq * DINq];
__device__ __nv_bfloat16 g_oh  [Bq * Tq * DMq];
__device__ __nv_bfloat16 g_ol  [Bq * Tq * DMq];
__device__ unsigned      g_qkvp[Bq * Tq * 3 * DMq];
__device__ __nv_bfloat16 g_hh  [Bq * Tq * DMq];
__device__ __nv_bfloat16 g_hl  [Bq * Tq * DMq];

// Weights split hi/lo, packed: b0w(256x1024), per layer wq|wk|wv|bw, b6w(157x256)
#define W_B0    0
#define W_L0    262144
#define W_PERL  (4 * 65536)
#define W_B6    (262144 + 5 * W_PERL)
#define W_TOTAL (W_B6 + NCq * DMq)
__device__ __nv_bfloat16 g_wh[W_TOTAL];
__device__ __nv_bfloat16 g_wl[W_TOTAL];

// ---------------------------------------------------------------------------
// Helpers
// ---------------------------------------------------------------------------
__device__ __forceinline__ unsigned smem_u32(const void* p) {
    unsigned a;
    asm("{ .reg .u64 t; cvta.to.shared.u64 t, %1; cvt.u32.u64 %0, t; }" : "=r"(a) : "l"(p));
    return a;
}
__device__ __forceinline__ void split1(float v, __nv_bfloat16& h, __nv_bfloat16& l) {
    h = __float2bfloat16_rn(v);
    l = __float2bfloat16_rn(v - __bfloat162float(h));
}
__device__ __forceinline__ unsigned packu(float v) {
    __nv_bfloat16 h, l;
    split1(v, h, l);
    return (unsigned)__bfloat16_as_ushort(h) | ((unsigned)__bfloat16_as_ushort(l) << 16);
}
__device__ __forceinline__ float unpacku(unsigned u) {
    return __bfloat162float(__ushort_as_bfloat16((unsigned short)(u & 0xffffu))) +
           __bfloat162float(__ushort_as_bfloat16((unsigned short)(u >> 16)));
}
__device__ __forceinline__ void ldmat4(unsigned (&r)[4], unsigned addr) {
    asm volatile("ldmatrix.sync.aligned.m8n8.x4.shared.b16 {%0,%1,%2,%3}, [%4];"
                 : "=r"(r[0]), "=r"(r[1]), "=r"(r[2]), "=r"(r[3]) : "r"(addr));
}
__device__ __forceinline__ void mma16816(float (&c)[4], const unsigned (&a)[4],
                                         unsigned b0, unsigned b1) {
    asm volatile(
        "mma.sync.aligned.m16n8k16.row.col.f32.bf16.bf16.f32 "
        "{%0,%1,%2,%3}, {%4,%5,%6,%7}, {%8,%9}, {%0,%1,%2,%3};"
        : "+f"(c[0]), "+f"(c[1]), "+f"(c[2]), "+f"(c[3])
        : "r"(a[0]), "r"(a[1]), "r"(a[2]), "r"(a[3]), "r"(b0), "r"(b1));
}
// L1-bypass async copy: tiles have zero L1 reuse, keep L1 for LDSM traffic.
__device__ __forceinline__ void cp16(unsigned saddr, const void* gaddr, int srcsz) {
    asm volatile("cp.async.cg.shared.global [%0], [%1], 16, %2;"
                 :: "r"(saddr), "l"(gaddr), "r"(srcsz) : "memory");
}
#define CP_COMMIT() asm volatile("cp.async.commit_group;" ::: "memory")
#define CP_WAIT1()  asm volatile("cp.async.wait_group 1;" ::: "memory")

// ---------------------------------------------------------------------------
// GEMM: D[o,t] = sum_i W[o,i] * Act[b,t,i]   (split-bf16 x3, mma.sync)
// Block 128(M=o) x 128(N=t), K-chunk 32, 256 threads (8 warps, 4m x 2n),
// warp tile 32x64. cp.async 3-stage pipeline, 64B stride + XOR swizzle.
// EPI: 0 plain -> packed uint32 [b,t,o] stride OSTR
//      1 +bias -> bf16 hi/lo
//      2 (resid+D+bias)*mask -> bf16 hi/lo
//      3 (D+bias)*mask -> fp32 [b,o,t]
// ---------------------------------------------------------------------------
#define TILE_P   8192               // one 128x32 bf16 part (64B stride)
#define STAGE    32768              // A.hi A.lo B.hi B.lo
#define SMEM_TOT 98304              // 3 stages

template <int EPI, int KTOT, int OROWS, int OSTR>
__global__ void __launch_bounds__(256, 2)
gemm_mma(const __nv_bfloat16* __restrict__ Whi, const __nv_bfloat16* __restrict__ Wlo,
         const __nv_bfloat16* __restrict__ Ahi, const __nv_bfloat16* __restrict__ Alo,
         const float* __restrict__ bias, const float* __restrict__ mask,
         const __nv_bfloat16* __restrict__ Rhi, const __nv_bfloat16* __restrict__ Rlo,
         __nv_bfloat16* __restrict__ Ohi, __nv_bfloat16* __restrict__ Olo,
         float* __restrict__ OF)
{
    extern __shared__ char smem[];
    const unsigned sb = smem_u32(smem);
    const int tid  = threadIdx.x;
    const int lane = tid & 31, wid = tid >> 5;
    const int bT = blockIdx.x * 128;
    const int bO = blockIdx.y * 128;
    const int b  = blockIdx.z;
    const int m0 = (wid & 3) * 32;
    const int n0 = (wid >> 2) * 64;

    constexpr bool GUARDA = (OROWS & 127) != 0;
    constexpr int NCH = KTOT / 32;

    const __nv_bfloat16* Bh = Ahi + ((size_t)b * Tq + bT) * KTOT;
    const __nv_bfloat16* Bl = Alo + ((size_t)b * Tq + bT) * KTOT;

    // ldmatrix per-thread swizzled offsets (64B stride, chunk ^= (row>>1)&3)
    const int raA  = lane & 15;
    const int xorA = (raA >> 1) & 3;
    const int laA[2] = { raA * 64 + ((((lane >> 4)    ) ^ xorA) << 4),
                         raA * 64 + ((((lane >> 4) + 2) ^ xorA) << 4) };
    const int matv = lane >> 3;
    const int rbB  = (lane & 7) + ((matv >> 1) * 8);
    const int xorB = (rbB >> 1) & 3;
    const int lbB[2] = { rbB * 64 + ((((matv & 1)    ) ^ xorB) << 4),
                         rbB * 64 + ((((matv & 1) + 2) ^ xorB) << 4) };

    float acc[2][8][4];
#pragma unroll
    for (int i = 0; i < 2; i++)
#pragma unroll
        for (int j = 0; j < 8; j++)
#pragma unroll
            for (int l = 0; l < 4; l++) acc[i][j][l] = 0.f;

    // ---- async tile issue (always commits exactly one group) ----
    auto issue = [&](int ch, int stg) {
        if (ch < NCH) {
            const int k0 = ch * 32;
            const unsigned st = sb + stg * STAGE;
#pragma unroll
            for (int i = 0; i < 2; i++) {
                const int task = i * 256 + tid;
                const int row = task >> 2, c = task & 3;
                const unsigned soff = (unsigned)(row * 64 + ((c ^ ((row >> 1) & 3)) << 4));
                int asz = 16;
                size_t aoff = (size_t)(bO + row) * KTOT + k0 + c * 8;
                if (GUARDA && (bO + row >= OROWS)) { asz = 0; aoff = 0; }
                cp16(st + soff,              Whi + aoff, asz);
                cp16(st + TILE_P + soff,     Wlo + aoff, asz);
                const size_t boff = (size_t)row * KTOT + k0 + c * 8;
                cp16(st + 2 * TILE_P + soff, Bh + boff, 16);
                cp16(st + 3 * TILE_P + soff, Bl + boff, 16);
            }
        }
        CP_COMMIT();
    };

    issue(0, 0);
    issue(1, 1);

    int cs = 0, is = 2;
#pragma unroll 1
    for (int ch = 0; ch < NCH; ch++) {
        CP_WAIT1();
        __syncthreads();
        issue(ch + 2, is);
        is = (is == 2) ? 0 : is + 1;

        const unsigned Ah_ = sb + cs * STAGE;
        const unsigned Al_ = Ah_ + TILE_P;
        const unsigned Bh_ = Ah_ + 2 * TILE_P;
        const unsigned Bl_ = Ah_ + 3 * TILE_P;
        cs = (cs == 2) ? 0 : cs + 1;

#pragma unroll
        for (int kk = 0; kk < 2; kk++) {
            unsigned ah[2][4], al[2][4];
            ldmat4(ah[0], Ah_ + (m0     ) * 64 + laA[kk]);
            ldmat4(ah[1], Ah_ + (m0 + 16) * 64 + laA[kk]);
            ldmat4(al[0], Al_ + (m0     ) * 64 + laA[kk]);
            ldmat4(al[1], Al_ + (m0 + 16) * 64 + laA[kk]);
#pragma unroll
            for (int nt2 = 0; nt2 < 4; nt2++) {
                unsigned bh[4], bl[4];
                ldmat4(bh, Bh_ + (n0 + nt2 * 16) * 64 + lbB[kk]);
                ldmat4(bl, Bl_ + (n0 + nt2 * 16) * 64 + lbB[kk]);
                mma16816(acc[0][nt2 * 2 + 0], ah[0], bh[0], bh[1]);
                mma16816(acc[0][nt2 * 2 + 1], ah[0], bh[2], bh[3]);
                mma16816(acc[1][nt2 * 2 + 0], ah[1], bh[0], bh[1]);
                mma16816(acc[1][nt2 * 2 + 1], ah[1], bh[2], bh[3]);
                mma16816(acc[0][nt2 * 2 + 0], ah[0], bl[0], bl[1]);
                mma16816(acc[0][nt2 * 2 + 1], ah[0], bl[2], bl[3]);
                mma16816(acc[1][nt2 * 2 + 0], ah[1], bl[0], bl[1]);
                mma16816(acc[1][nt2 * 2 + 1], ah[1], bl[2], bl[3]);
                mma16816(acc[0][nt2 * 2 + 0], al[0], bh[0], bh[1]);
                mma16816(acc[0][nt2 * 2 + 1], al[0], bh[2], bh[3]);
                mma16816(acc[1][nt2 * 2 + 0], al[1], bh[0], bh[1]);
                mma16816(acc[1][nt2 * 2 + 1], al[1], bh[2], bh[3]);
            }
        }
    }

    // ---- epilogue ----
    const int g = lane >> 2, tig = lane & 3;
#pragma unroll
    for (int mi = 0; mi < 2; mi++) {
#pragma unroll
        for (int pr = 0; pr < 2; pr++) {
            const int o = bO + m0 + mi * 16 + g + pr * 8;
            float bs = 0.f;
            if (EPI >= 1) bs = (!GUARDA || o < OROWS) ? bias[o] : 0.f;
#pragma unroll
            for (int nt = 0; nt < 8; nt++) {
                const int t = bT + n0 + nt * 8 + 2 * tig;
                float v0 = acc[mi][nt][pr * 2 + 0] + bs;
                float v1 = acc[mi][nt][pr * 2 + 1] + bs;
                if (EPI == 0) {
                    unsigned* Op = (unsigned*)Ohi;
                    const size_t i0 = ((size_t)b * Tq + t) * OSTR + o;
                    Op[i0]        = packu(v0);
                    Op[i0 + OSTR] = packu(v1);
                } else if (EPI == 3) {
                    if (!GUARDA || o < OROWS) {
                        const float mk0 = mask[(size_t)b * Tq + t];
                        const float mk1 = mask[(size_t)b * Tq + t + 1];
                        *(float2*)(OF + ((size_t)b * OROWS + o) * Tq + t) =
                            make_float2(v0 * mk0, v1 * mk1);
                    }
                } else {
                    const size_t i0 = ((size_t)b * Tq + t) * OSTR + o;
                    if (EPI == 2) {
                        const float mk0 = mask[(size_t)b * Tq + t];
                        const float mk1 = mask[(size_t)b * Tq + t + 1];
                        float r0 = __bfloat162float(Rhi[i0]) + __bfloat162float(Rlo[i0]);
                        float r1 = __bfloat162float(Rhi[i0 + OSTR]) + __bfloat162float(Rlo[i0 + OSTR]);
                        v0 = (r0 + v0) * mk0;
                        v1 = (r1 + v1) * mk1;
                    }
                    __nv_bfloat16 h0, l0, h1, l1;
                    split1(v0, h0, l0);
                    split1(v1, h1, l1);
                    Ohi[i0] = h0; Olo[i0] = l0;
                    Ohi[i0 + OSTR] = h1; Olo[i0 + OSTR] = l1;
                }
            }
        }
    }
}

// ---------------------------------------------------------------------------
// x transpose + split: [B, DIN, T] fp32 -> [B, T, DIN] bf16 hi/lo
// ---------------------------------------------------------------------------
__global__ __launch_bounds__(256)
void xpose_kernel(const float* __restrict__ x,
                  __nv_bfloat16* __restrict__ xh, __nv_bfloat16* __restrict__ xl)
{
    __shared__ float s[32][33];
    const int t0 = blockIdx.x * 32, i0 = blockIdx.y * 32, b = blockIdx.z;
    const int tx = threadIdx.x & 31, ty = threadIdx.x >> 5;
    const float* xb = x + (size_t)b * DINq * Tq;
#pragma unroll
    for (int kk = 0; kk < 4; kk++)
        s[ty + 8 * kk][tx] = xb[(size_t)(i0 + ty + 8 * kk) * Tq + t0 + tx];
    __syncthreads();
#pragma unroll
    for (int kk = 0; kk < 4; kk++) {
        const float v = s[tx][ty + 8 * kk];
        const size_t idx = ((size_t)b * Tq + t0 + ty + 8 * kk) * DINq + i0 + tx;
        __nv_bfloat16 h, l;
        split1(v, h, l);
        xh[idx] = h; xl[idx] = l;
    }
}

// ---------------------------------------------------------------------------
// Weight split
// ---------------------------------------------------------------------------
struct WPtrs { const float* p[22]; };

__global__ __launch_bounds__(256)
void convw_kernel(WPtrs wp, __nv_bfloat16* __restrict__ wh, __nv_bfloat16* __restrict__ wl)
{
    const int idx = blockIdx.x * 256 + threadIdx.x;
    int off = 0;
#pragma unroll
    for (int m = 0; m < 22; m++) {
        const int sz = (m == 0) ? 262144 : ((m == 21) ? NCq * DMq : 65536);
        if (idx < off + sz) {
            __nv_bfloat16 h, l;
            split1(wp.p[m][idx - off], h, l);
            wh[idx] = h; wl[idx] = l;
            return;
        }
        off += sz;
    }
}

// ---------------------------------------------------------------------------
// Dilated 3-tap softmax attention + ReLU, reading packed qkv [B,T,768]
// ---------------------------------------------------------------------------
__device__ __forceinline__ void load4p(const unsigned* __restrict__ p, size_t e, float (&o)[4])
{
    const uint4 u = *(const uint4*)(p + e);
    o[0] = unpacku(u.x);
    o[1] = unpacku(u.y);
    o[2] = unpacku(u.z);
    o[3] = unpacku(u.w);
}

__device__ __forceinline__ float attn1(float q, float k0, float k1, float k2,
                                       float v0, float v1, float v2)
{
    const float s0 = q * k0, s1 = q * k1, s2 = q * k2;
    const float mx = fmaxf(s0, fmaxf(s1, s2));
    const float e0 = __expf(s0 - mx), e1 = __expf(s1 - mx), e2 = __expf(s2 - mx);
    return fmaxf((e0 * v0 + e1 * v1 + e2 * v2) / (e0 + e1 + e2), 0.f);
}

__global__ __launch_bounds__(256)
void attn_kernel(const unsigned* __restrict__ qkvp,
                 __nv_bfloat16* __restrict__ hh, __nv_bfloat16* __restrict__ hl, int d)
{
    const size_t gid = (size_t)blockIdx.x * 256 + threadIdx.x;
    const int c4 = (int)(gid & 63);
    const int t  = (int)((gid >> 6) & (Tq - 1));
    const int b  = (int)(gid >> 18);
    const size_t rq = ((size_t)b * Tq + t) * 768 + c4 * 4;
    const long long off = (long long)d * 768;

    float q[4], k1[4], v1[4];
    load4p(qkvp, rq,       q);
    load4p(qkvp, rq + 256, k1);
    load4p(qkvp, rq + 512, v1);
    float k0[4] = {0, 0, 0, 0}, v0[4] = {0, 0, 0, 0};
    float k2[4] = {0, 0, 0, 0}, v2[4] = {0, 0, 0, 0};
    if (t - d >= 0) { load4p(qkvp, rq + 256 - off, k0); load4p(qkvp, rq + 512 - off, v0); }
    if (t + d < Tq) { load4p(qkvp, rq + 256 + off, k2); load4p(qkvp, rq + 512 + off, v2); }

    const size_t e = ((size_t)b * Tq + t) * DMq + c4 * 4;
    __nv_bfloat16 rh[4], rl[4];
#pragma unroll
    for (int c = 0; c < 4; c++) {
        const float r = attn1(q[c], k0[c], k1[c], k2[c], v0[c], v1[c], v2[c]);
        split1(r, rh[c], rl[c]);
    }
    *(__nv_bfloat162*)(hh + e)     = __nv_bfloat162(rh[0], rh[1]);
    *(__nv_bfloat162*)(hh + e + 2) = __nv_bfloat162(rh[2], rh[3]);
    *(__nv_bfloat162*)(hl + e)     = __nv_bfloat162(rl[0], rl[1]);
    *(__nv_bfloat162*)(hl + e + 2) = __nv_bfloat162(rl[2], rl[3]);
}

// ---------------------------------------------------------------------------
// Launch: batch split B=8 -> 2 streams x 4 batches (fork-join capture pattern)
// ---------------------------------------------------------------------------
extern "C" void kernel_launch(void* const* d_in, const int* in_sizes, int n_in,
                              void* d_out, int out_size)
{
    const float* x    = (const float*)d_in[0];
    const float* mask = (const float*)d_in[1];
    const float* b0b  = (const float*)d_in[3];
    const float* b6b  = (const float*)d_in[30];

    __nv_bfloat16 *xh, *xl, *oh, *ol, *hh, *hl, *wh, *wl;
    unsigned *qkvp;
    cudaGetSymbolAddress((void**)&xh, g_xh);      cudaGetSymbolAddress((void**)&xl, g_xl);
    cudaGetSymbolAddress((void**)&oh, g_oh);      cudaGetSymbolAddress((void**)&ol, g_ol);
    cudaGetSymbolAddress((void**)&qkvp, g_qkvp);
    cudaGetSymbolAddress((void**)&hh, g_hh);      cudaGetSymbolAddress((void**)&hl, g_hl);
    cudaGetSymbolAddress((void**)&wh, g_wh);      cudaGetSymbolAddress((void**)&wl, g_wl);

    cudaFuncSetAttribute(gemm_mma<1, DINq, DMq, DMq>,        cudaFuncAttributeMaxDynamicSharedMemorySize, SMEM_TOT);
    cudaFuncSetAttribute(gemm_mma<0, DMq, 3 * DMq, 3 * DMq>, cudaFuncAttributeMaxDynamicSharedMemorySize, SMEM_TOT);
    cudaFuncSetAttribute(gemm_mma<2, DMq, DMq, DMq>,         cudaFuncAttributeMaxDynamicSharedMemorySize, SMEM_TOT);
    cudaFuncSetAttribute(gemm_mma<3, DMq, NCq, DMq>,         cudaFuncAttributeMaxDynamicSharedMemorySize, SMEM_TOT);

    // split weights (shared by both streams)
    WPtrs wp;
    wp.p[0] = (const float*)d_in[2];
    for (int l = 0; l < 5; l++) {
        wp.p[1 + 4 * l + 0] = (const float*)d_in[4 + 5 * l + 0];
        wp.p[1 + 4 * l + 1] = (const float*)d_in[4 + 5 * l + 1];
        wp.p[1 + 4 * l + 2] = (const float*)d_in[4 + 5 * l + 2];
        wp.p[1 + 4 * l + 3] = (const float*)d_in[4 + 5 * l + 3];
    }
    wp.p[21] = (const float*)d_in[29];
    convw_kernel<<<W_TOTAL / 256, 256>>>(wp, wh, wl);

    // fork two worker streams off the main (capture) stream
    cudaStream_t st[2];
    cudaEvent_t ev_fork, ev_join0, ev_join1;
    cudaStreamCreateWithFlags(&st[0], cudaStreamNonBlocking);
    cudaStreamCreateWithFlags(&st[1], cudaStreamNonBlocking);
    cudaEventCreateWithFlags(&ev_fork,  cudaEventDisableTiming);
    cudaEventCreateWithFlags(&ev_join0, cudaEventDisableTiming);
    cudaEventCreateWithFlags(&ev_join1, cudaEventDisableTiming);
    cudaEventRecord(ev_fork, 0);
    cudaStreamWaitEvent(st[0], ev_fork, 0);
    cudaStreamWaitEvent(st[1], ev_fork, 0);

    const int dils[5] = {1, 2, 4, 8, 16};
    const int HB = Bq / 2;   // 4 batches per stream

    for (int s = 0; s < 2; s++) {
        cudaStream_t S = st[s];
        const size_t b0 = (size_t)s * HB;

        // per-stream pointer offsets
        const float*    x_    = x    + b0 * DINq * Tq;
        const float*    mask_ = mask + b0 * Tq;
        __nv_bfloat16*  xh_   = xh   + b0 * Tq * DINq;
        __nv_bfloat16*  xl_   = xl   + b0 * Tq * DINq;
        __nv_bfloat16*  oh_   = oh   + b0 * Tq * DMq;
        __nv_bfloat16*  ol_   = ol   + b0 * Tq * DMq;
        unsigned*       qk_   = qkvp + b0 * Tq * 3 * DMq;
        __nv_bfloat16*  hh_   = hh   + b0 * Tq * DMq;
        __nv_bfloat16*  hl_   = hl   + b0 * Tq * DMq;
        float*          of_   = (float*)d_out + b0 * NCq * Tq;

        const dim3 thr(256);
        const dim3 g_xp (Tq / 32, DINq / 32, HB);
        const dim3 g_dm (Tq / 128, DMq / 128, HB);             // (32, 2, 4)
        const dim3 g_qkv(Tq / 128, 3 * DMq / 128, HB);         // (32, 6, 4)
        const dim3 g_nc (Tq / 128, (NCq + 127) / 128, HB);     // (32, 2, 4)
        const int  g_at = (HB * Tq * 64) / 256;                // 4096

        // transpose + split this stream's batches
        xpose_kernel<<<g_xp, thr, 0, S>>>(x_, xh_, xl_);

        // input GEMM
        gemm_mma<1, DINq, DMq, DMq><<<g_dm, thr, SMEM_TOT, S>>>(
            wh + W_B0, wl + W_B0, xh_, xl_, b0b, nullptr, nullptr, nullptr,
            oh_, ol_, nullptr);

        for (int l = 0; l < 5; l++) {
            const float* bb = (const float*)d_in[4 + 5 * l + 4];
            const int wqkv = W_L0 + l * W_PERL;
            const int bw   = wqkv + 3 * 65536;

            gemm_mma<0, DMq, 3 * DMq, 3 * DMq><<<g_qkv, thr, SMEM_TOT, S>>>(
                wh + wqkv, wl + wqkv, oh_, ol_, nullptr, nullptr, nullptr, nullptr,
                (__nv_bfloat16*)qk_, nullptr, nullptr);

            attn_kernel<<<g_at, thr, 0, S>>>(qk_, hh_, hl_, dils[l]);

            gemm_mma<2, DMq, DMq, DMq><<<g_dm, thr, SMEM_TOT, S>>>(
                wh + bw, wl + bw, hh_, hl_, bb, mask_, oh_, ol_, oh_, ol_, nullptr);
        }

        gemm_mma<3, DMq, NCq, DMq><<<g_nc, thr, SMEM_TOT, S>>>(
            wh + W_B6, wl + W_B6, oh_, ol_, b6b, mask_, nullptr, nullptr,
            nullptr, nullptr, of_);
    }

    // join both streams back into the main stream
    cudaEventRecord(ev_join0, st[0]);
    cudaEventRecord(ev_join1, st[1]);
    cudaStreamWaitEvent(0, ev_join0, 0);
    cudaStreamWaitEvent(0, ev_join1, 0);

    cudaEventDestroy(ev_fork);
    cudaEventDestroy(ev_join0);
    cudaEventDestroy(ev_join1);
    cudaStreamDestroy(st[0]);
    cudaStreamDestroy(st[1]);
}

// round 11
// speedup vs baseline: 1.4947x; 1.0105x over previous
#include <cuda_runtime.h>
#include <cuda_bf16.h>

#define Bq   8
#define Tq   4096
#define DINq 1024
#define DMq  256
#define NCq  157

// ---------------------------------------------------------------------------
// Scratch: activations in [B, T, C] (K-major for MMA B operand)
// GEMM inputs (out, h, xt): separate bf16 hi/lo planes (pre-split for cp.async)
// qkv (GEMM output -> attention only): packed uint32 = hi | lo<<16
// ---------------------------------------------------------------------------
__device__ __nv_bfloat16 g_xh  [Bq * Tq * DINq];
__device__ __nv_bfloat16 g_xl  [Bq * Tq * DINq];
__device__ __nv_bfloat16 g_oh  [Bq * Tq * DMq];
__device__ __nv_bfloat16 g_ol  [Bq * Tq * DMq];
__device__ unsigned      g_qkvp[Bq * Tq * 3 * DMq];
__device__ __nv_bfloat16 g_hh  [Bq * Tq * DMq];
__device__ __nv_bfloat16 g_hl  [Bq * Tq * DMq];

// Weights split hi/lo, packed: b0w(256x1024), per layer wq|wk|wv|bw, b6w(157x256)
#define W_B0    0
#define W_L0    262144
#define W_PERL  (4 * 65536)
#define W_B6    (262144 + 5 * W_PERL)
#define W_TOTAL (W_B6 + NCq * DMq)
__device__ __nv_bfloat16 g_wh[W_TOTAL];
__device__ __nv_bfloat16 g_wl[W_TOTAL];

// ---------------------------------------------------------------------------
// Helpers
// ---------------------------------------------------------------------------
__device__ __forceinline__ unsigned smem_u32(const void* p) {
    unsigned a;
    asm("{ .reg .u64 t; cvta.to.shared.u64 t, %1; cvt.u32.u64 %0, t; }" : "=r"(a) : "l"(p));
    return a;
}
__device__ __forceinline__ void split1(float v, __nv_bfloat16& h, __nv_bfloat16& l) {
    h = __float2bfloat16_rn(v);
    l = __float2bfloat16_rn(v - __bfloat162float(h));
}
__device__ __forceinline__ unsigned packu(float v) {
    __nv_bfloat16 h, l;
    split1(v, h, l);
    return (unsigned)__bfloat16_as_ushort(h) | ((unsigned)__bfloat16_as_ushort(l) << 16);
}
__device__ __forceinline__ float unpacku(unsigned u) {
    return __bfloat162float(__ushort_as_bfloat16((unsigned short)(u & 0xffffu))) +
           __bfloat162float(__ushort_as_bfloat16((unsigned short)(u >> 16)));
}
__device__ __forceinline__ void ldmat4(unsigned (&r)[4], unsigned addr) {
    asm volatile("ldmatrix.sync.aligned.m8n8.x4.shared.b16 {%0,%1,%2,%3}, [%4];"
                 : "=r"(r[0]), "=r"(r[1]), "=r"(r[2]), "=r"(r[3]) : "r"(addr));
}
__device__ __forceinline__ void mma16816(float (&c)[4], const unsigned (&a)[4],
                                         unsigned b0, unsigned b1) {
    asm volatile(
        "mma.sync.aligned.m16n8k16.row.col.f32.bf16.bf16.f32 "
        "{%0,%1,%2,%3}, {%4,%5,%6,%7}, {%8,%9}, {%0,%1,%2,%3};"
        : "+f"(c[0]), "+f"(c[1]), "+f"(c[2]), "+f"(c[3])
        : "r"(a[0]), "r"(a[1]), "r"(a[2]), "r"(a[3]), "r"(b0), "r"(b1));
}
// L1-bypass async copy: tiles have zero L1 reuse, keep L1 for LDSM traffic.
__device__ __forceinline__ void cp16(unsigned saddr, const void* gaddr, int srcsz) {
    asm volatile("cp.async.cg.shared.global [%0], [%1], 16, %2;"
                 :: "r"(saddr), "l"(gaddr), "r"(srcsz) : "memory");
}
#define CP_COMMIT() asm volatile("cp.async.commit_group;" ::: "memory")
#define CP_WAIT1()  asm volatile("cp.async.wait_group 1;" ::: "memory")

// ---------------------------------------------------------------------------
// GEMM: D[o,t] = sum_i W[o,i] * Act[b,t,i]   (split-bf16 x3, mma.sync)
// Block 128(M=o) x 128(N=t), K-chunk 32, 256 threads (8 warps, 4m x 2n),
// warp tile 32x64. cp.async 3-stage pipeline, 64B stride + XOR swizzle.
// EPI: 0 plain -> packed uint32 [b,t,o] stride OSTR
//      1 +bias -> bf16 hi/lo
//      2 (resid+D+bias)*mask -> bf16 hi/lo
//      3 (D+bias)*mask -> fp32 [b,o,t]
// ---------------------------------------------------------------------------
#define TILE_P   8192               // one 128x32 bf16 part (64B stride)
#define STAGE    32768              // A.hi A.lo B.hi B.lo
#define SMEM_TOT 98304              // 3 stages

template <int EPI, int KTOT, int OROWS, int OSTR>
__global__ void __launch_bounds__(256, 2)
gemm_mma(const __nv_bfloat16* __restrict__ Whi, const __nv_bfloat16* __restrict__ Wlo,
         const __nv_bfloat16* __restrict__ Ahi, const __nv_bfloat16* __restrict__ Alo,
         const float* __restrict__ bias, const float* __restrict__ mask,
         const __nv_bfloat16* __restrict__ Rhi, const __nv_bfloat16* __restrict__ Rlo,
         __nv_bfloat16* __restrict__ Ohi, __nv_bfloat16* __restrict__ Olo,
         float* __restrict__ OF)
{
    extern __shared__ char smem[];
    const unsigned sb = smem_u32(smem);
    const int tid  = threadIdx.x;
    const int lane = tid & 31, wid = tid >> 5;
    const int bT = blockIdx.x * 128;
    const int bO = blockIdx.y * 128;
    const int b  = blockIdx.z;
    const int m0 = (wid & 3) * 32;
    const int n0 = (wid >> 2) * 64;

    constexpr bool GUARDA = (OROWS & 127) != 0;
    constexpr int NCH = KTOT / 32;

    const __nv_bfloat16* Bh = Ahi + ((size_t)b * Tq + bT) * KTOT;
    const __nv_bfloat16* Bl = Alo + ((size_t)b * Tq + bT) * KTOT;

    // ldmatrix per-thread swizzled offsets (64B stride, chunk ^= (row>>1)&3)
    const int raA  = lane & 15;
    const int xorA = (raA >> 1) & 3;
    const int laA[2] = { raA * 64 + ((((lane >> 4)    ) ^ xorA) << 4),
                         raA * 64 + ((((lane >> 4) + 2) ^ xorA) << 4) };
    const int matv = lane >> 3;
    const int rbB  = (lane & 7) + ((matv >> 1) * 8);
    const int xorB = (rbB >> 1) & 3;
    const int lbB[2] = { rbB * 64 + ((((matv & 1)    ) ^ xorB) << 4),
                         rbB * 64 + ((((matv & 1) + 2) ^ xorB) << 4) };

    float acc[2][8][4];
#pragma unroll
    for (int i = 0; i < 2; i++)
#pragma unroll
        for (int j = 0; j < 8; j++)
#pragma unroll
            for (int l = 0; l < 4; l++) acc[i][j][l] = 0.f;

    // ---- async tile issue (always commits exactly one group) ----
    auto issue = [&](int ch, int stg) {
        if (ch < NCH) {
            const int k0 = ch * 32;
            const unsigned st = sb + stg * STAGE;
#pragma unroll
            for (int i = 0; i < 2; i++) {
                const int task = i * 256 + tid;
                const int row = task >> 2, c = task & 3;
                const unsigned soff = (unsigned)(row * 64 + ((c ^ ((row >> 1) & 3)) << 4));
                int asz = 16;
                size_t aoff = (size_t)(bO + row) * KTOT + k0 + c * 8;
                if (GUARDA && (bO + row >= OROWS)) { asz = 0; aoff = 0; }
                cp16(st + soff,              Whi + aoff, asz);
                cp16(st + TILE_P + soff,     Wlo + aoff, asz);
                const size_t boff = (size_t)row * KTOT + k0 + c * 8;
                cp16(st + 2 * TILE_P + soff, Bh + boff, 16);
                cp16(st + 3 * TILE_P + soff, Bl + boff, 16);
            }
        }
        CP_COMMIT();
    };

    issue(0, 0);
    issue(1, 1);

    int cs = 0, is = 2;
#pragma unroll 1
    for (int ch = 0; ch < NCH; ch++) {
        CP_WAIT1();
        __syncthreads();
        issue(ch + 2, is);
        is = (is == 2) ? 0 : is + 1;

        const unsigned Ah_ = sb + cs * STAGE;
        const unsigned Al_ = Ah_ + TILE_P;
        const unsigned Bh_ = Ah_ + 2 * TILE_P;
        const unsigned Bl_ = Ah_ + 3 * TILE_P;
        cs = (cs == 2) ? 0 : cs + 1;

#pragma unroll
        for (int kk = 0; kk < 2; kk++) {
            unsigned ah[2][4], al[2][4];
            ldmat4(ah[0], Ah_ + (m0     ) * 64 + laA[kk]);
            ldmat4(ah[1], Ah_ + (m0 + 16) * 64 + laA[kk]);
            ldmat4(al[0], Al_ + (m0     ) * 64 + laA[kk]);
            ldmat4(al[1], Al_ + (m0 + 16) * 64 + laA[kk]);
#pragma unroll
            for (int nt2 = 0; nt2 < 4; nt2++) {
                unsigned bh[4], bl[4];
                ldmat4(bh, Bh_ + (n0 + nt2 * 16) * 64 + lbB[kk]);
                ldmat4(bl, Bl_ + (n0 + nt2 * 16) * 64 + lbB[kk]);
                mma16816(acc[0][nt2 * 2 + 0], ah[0], bh[0], bh[1]);
                mma16816(acc[0][nt2 * 2 + 1], ah[0], bh[2], bh[3]);
                mma16816(acc[1][nt2 * 2 + 0], ah[1], bh[0], bh[1]);
                mma16816(acc[1][nt2 * 2 + 1], ah[1], bh[2], bh[3]);
                mma16816(acc[0][nt2 * 2 + 0], ah[0], bl[0], bl[1]);
                mma16816(acc[0][nt2 * 2 + 1], ah[0], bl[2], bl[3]);
                mma16816(acc[1][nt2 * 2 + 0], ah[1], bl[0], bl[1]);
                mma16816(acc[1][nt2 * 2 + 1], ah[1], bl[2], bl[3]);
                mma16816(acc[0][nt2 * 2 + 0], al[0], bh[0], bh[1]);
                mma16816(acc[0][nt2 * 2 + 1], al[0], bh[2], bh[3]);
                mma16816(acc[1][nt2 * 2 + 0], al[1], bh[0], bh[1]);
                mma16816(acc[1][nt2 * 2 + 1], al[1], bh[2], bh[3]);
            }
        }
    }

    // ---- epilogue ----
    const int g = lane >> 2, tig = lane & 3;
#pragma unroll
    for (int mi = 0; mi < 2; mi++) {
#pragma unroll
        for (int pr = 0; pr < 2; pr++) {
            const int o = bO + m0 + mi * 16 + g + pr * 8;
            float bs = 0.f;
            if (EPI >= 1) bs = (!GUARDA || o < OROWS) ? bias[o] : 0.f;
#pragma unroll
            for (int nt = 0; nt < 8; nt++) {
                const int t = bT + n0 + nt * 8 + 2 * tig;
                float v0 = acc[mi][nt][pr * 2 + 0] + bs;
                float v1 = acc[mi][nt][pr * 2 + 1] + bs;
                if (EPI == 0) {
                    unsigned* Op = (unsigned*)Ohi;
                    const size_t i0 = ((size_t)b * Tq + t) * OSTR + o;
                    Op[i0]        = packu(v0);
                    Op[i0 + OSTR] = packu(v1);
                } else if (EPI == 3) {
                    if (!GUARDA || o < OROWS) {
                        const float mk0 = mask[(size_t)b * Tq + t];
                        const float mk1 = mask[(size_t)b * Tq + t + 1];
                        *(float2*)(OF + ((size_t)b * OROWS + o) * Tq + t) =
                            make_float2(v0 * mk0, v1 * mk1);
                    }
                } else {
                    const size_t i0 = ((size_t)b * Tq + t) * OSTR + o;
                    if (EPI == 2) {
                        const float mk0 = mask[(size_t)b * Tq + t];
                        const float mk1 = mask[(size_t)b * Tq + t + 1];
                        float r0 = __bfloat162float(Rhi[i0]) + __bfloat162float(Rlo[i0]);
                        float r1 = __bfloat162float(Rhi[i0 + OSTR]) + __bfloat162float(Rlo[i0 + OSTR]);
                        v0 = (r0 + v0) * mk0;
                        v1 = (r1 + v1) * mk1;
                    }
                    __nv_bfloat16 h0, l0, h1, l1;
                    split1(v0, h0, l0);
                    split1(v1, h1, l1);
                    Ohi[i0] = h0; Olo[i0] = l0;
                    Ohi[i0 + OSTR] = h1; Olo[i0 + OSTR] = l1;
                }
            }
        }
    }
}

// ---------------------------------------------------------------------------
// x transpose + split: [B, DIN, T] fp32 -> [B, T, DIN] bf16 hi/lo
// ---------------------------------------------------------------------------
__global__ __launch_bounds__(256)
void xpose_kernel(const float* __restrict__ x,
                  __nv_bfloat16* __restrict__ xh, __nv_bfloat16* __restrict__ xl)
{
    __shared__ float s[32][33];
    const int t0 = blockIdx.x * 32, i0 = blockIdx.y * 32, b = blockIdx.z;
    const int tx = threadIdx.x & 31, ty = threadIdx.x >> 5;
    const float* xb = x + (size_t)b * DINq * Tq;
#pragma unroll
    for (int kk = 0; kk < 4; kk++)
        s[ty + 8 * kk][tx] = xb[(size_t)(i0 + ty + 8 * kk) * Tq + t0 + tx];
    __syncthreads();
#pragma unroll
    for (int kk = 0; kk < 4; kk++) {
        const float v = s[tx][ty + 8 * kk];
        const size_t idx = ((size_t)b * Tq + t0 + ty + 8 * kk) * DINq + i0 + tx;
        __nv_bfloat16 h, l;
        split1(v, h, l);
        xh[idx] = h; xl[idx] = l;
    }
}

// ---------------------------------------------------------------------------
// Weight split
// ---------------------------------------------------------------------------
struct WPtrs { const float* p[22]; };

__global__ __launch_bounds__(256)
void convw_kernel(WPtrs wp, __nv_bfloat16* __restrict__ wh, __nv_bfloat16* __restrict__ wl)
{
    const int idx = blockIdx.x * 256 + threadIdx.x;
    int off = 0;
#pragma unroll
    for (int m = 0; m < 22; m++) {
        const int sz = (m == 0) ? 262144 : ((m == 21) ? NCq * DMq : 65536);
        if (idx < off + sz) {
            __nv_bfloat16 h, l;
            split1(wp.p[m][idx - off], h, l);
            wh[idx] = h; wl[idx] = l;
            return;
        }
        off += sz;
    }
}

// ---------------------------------------------------------------------------
// Dilated 3-tap softmax attention + ReLU, reading packed qkv [B,T,768]
// ---------------------------------------------------------------------------
__device__ __forceinline__ void load4p(const unsigned* __restrict__ p, size_t e, float (&o)[4])
{
    const uint4 u = *(const uint4*)(p + e);
    o[0] = unpacku(u.x);
    o[1] = unpacku(u.y);
    o[2] = unpacku(u.z);
    o[3] = unpacku(u.w);
}

__device__ __forceinline__ float attn1(float q, float k0, float k1, float k2,
                                       float v0, float v1, float v2)
{
    const float s0 = q * k0, s1 = q * k1, s2 = q * k2;
    const float mx = fmaxf(s0, fmaxf(s1, s2));
    const float e0 = __expf(s0 - mx), e1 = __expf(s1 - mx), e2 = __expf(s2 - mx);
    return fmaxf((e0 * v0 + e1 * v1 + e2 * v2) / (e0 + e1 + e2), 0.f);
}

__global__ __launch_bounds__(256)
void attn_kernel(const unsigned* __restrict__ qkvp,
                 __nv_bfloat16* __restrict__ hh, __nv_bfloat16* __restrict__ hl, int d)
{
    const size_t gid = (size_t)blockIdx.x * 256 + threadIdx.x;
    const int c4 = (int)(gid & 63);
    const int t  = (int)((gid >> 6) & (Tq - 1));
    const int b  = (int)(gid >> 18);
    const size_t rq = ((size_t)b * Tq + t) * 768 + c4 * 4;
    const long long off = (long long)d * 768;

    float q[4], k1[4], v1[4];
    load4p(qkvp, rq,       q);
    load4p(qkvp, rq + 256, k1);
    load4p(qkvp, rq + 512, v1);
    float k0[4] = {0, 0, 0, 0}, v0[4] = {0, 0, 0, 0};
    float k2[4] = {0, 0, 0, 0}, v2[4] = {0, 0, 0, 0};
    if (t - d >= 0) { load4p(qkvp, rq + 256 - off, k0); load4p(qkvp, rq + 512 - off, v0); }
    if (t + d < Tq) { load4p(qkvp, rq + 256 + off, k2); load4p(qkvp, rq + 512 + off, v2); }

    const size_t e = ((size_t)b * Tq + t) * DMq + c4 * 4;
    unsigned rh[2], rl[2];
#pragma unroll
    for (int c = 0; c < 2; c++) {
        __nv_bfloat16 h0, l0, h1, l1;
        split1(attn1(q[2*c],   k0[2*c],   k1[2*c],   k2[2*c],   v0[2*c],   v1[2*c],   v2[2*c]),   h0, l0);
        split1(attn1(q[2*c+1], k0[2*c+1], k1[2*c+1], k2[2*c+1], v0[2*c+1], v1[2*c+1], v2[2*c+1]), h1, l1);
        rh[c] = (unsigned)__bfloat16_as_ushort(h0) | ((unsigned)__bfloat16_as_ushort(h1) << 16);
        rl[c] = (unsigned)__bfloat16_as_ushort(l0) | ((unsigned)__bfloat16_as_ushort(l1) << 16);
    }
    *(uint2*)(hh + e) = make_uint2(rh[0], rh[1]);
    *(uint2*)(hl + e) = make_uint2(rl[0], rl[1]);
}

// ---------------------------------------------------------------------------
// Launch: batch split B=8 -> 4 streams x 2 batches (fork-join capture pattern)
// ---------------------------------------------------------------------------
#define NSTR 4

extern "C" void kernel_launch(void* const* d_in, const int* in_sizes, int n_in,
                              void* d_out, int out_size)
{
    const float* x    = (const float*)d_in[0];
    const float* mask = (const float*)d_in[1];
    const float* b0b  = (const float*)d_in[3];
    const float* b6b  = (const float*)d_in[30];

    __nv_bfloat16 *xh, *xl, *oh, *ol, *hh, *hl, *wh, *wl;
    unsigned *qkvp;
    cudaGetSymbolAddress((void**)&xh, g_xh);      cudaGetSymbolAddress((void**)&xl, g_xl);
    cudaGetSymbolAddress((void**)&oh, g_oh);      cudaGetSymbolAddress((void**)&ol, g_ol);
    cudaGetSymbolAddress((void**)&qkvp, g_qkvp);
    cudaGetSymbolAddress((void**)&hh, g_hh);      cudaGetSymbolAddress((void**)&hl, g_hl);
    cudaGetSymbolAddress((void**)&wh, g_wh);      cudaGetSymbolAddress((void**)&wl, g_wl);

    cudaFuncSetAttribute(gemm_mma<1, DINq, DMq, DMq>,        cudaFuncAttributeMaxDynamicSharedMemorySize, SMEM_TOT);
    cudaFuncSetAttribute(gemm_mma<0, DMq, 3 * DMq, 3 * DMq>, cudaFuncAttributeMaxDynamicSharedMemorySize, SMEM_TOT);
    cudaFuncSetAttribute(gemm_mma<2, DMq, DMq, DMq>,         cudaFuncAttributeMaxDynamicSharedMemorySize, SMEM_TOT);
    cudaFuncSetAttribute(gemm_mma<3, DMq, NCq, DMq>,         cudaFuncAttributeMaxDynamicSharedMemorySize, SMEM_TOT);

    // split weights (shared by all streams)
    WPtrs wp;
    wp.p[0] = (const float*)d_in[2];
    for (int l = 0; l < 5; l++) {
        wp.p[1 + 4 * l + 0] = (const float*)d_in[4 + 5 * l + 0];
        wp.p[1 + 4 * l + 1] = (const float*)d_in[4 + 5 * l + 1];
        wp.p[1 + 4 * l + 2] = (const float*)d_in[4 + 5 * l + 2];
        wp.p[1 + 4 * l + 3] = (const float*)d_in[4 + 5 * l + 3];
    }
    wp.p[21] = (const float*)d_in[29];
    convw_kernel<<<W_TOTAL / 256, 256>>>(wp, wh, wl);

    // fork worker streams off the main (capture) stream
    cudaStream_t st[NSTR];
    cudaEvent_t ev_fork, ev_join[NSTR];
    for (int s = 0; s < NSTR; s++) cudaStreamCreateWithFlags(&st[s], cudaStreamNonBlocking);
    cudaEventCreateWithFlags(&ev_fork, cudaEventDisableTiming);
    for (int s = 0; s < NSTR; s++) cudaEventCreateWithFlags(&ev_join[s], cudaEventDisableTiming);
    cudaEventRecord(ev_fork, 0);
    for (int s = 0; s < NSTR; s++) cudaStreamWaitEvent(st[s], ev_fork, 0);

    const int dils[5] = {1, 2, 4, 8, 16};
    const int HB = Bq / NSTR;   // 2 batches per stream

    for (int s = 0; s < NSTR; s++) {
        cudaStream_t S = st[s];
        const size_t b0 = (size_t)s * HB;

        const float*    x_    = x    + b0 * DINq * Tq;
        const float*    mask_ = mask + b0 * Tq;
        __nv_bfloat16*  xh_   = xh   + b0 * Tq * DINq;
        __nv_bfloat16*  xl_   = xl   + b0 * Tq * DINq;
        __nv_bfloat16*  oh_   = oh   + b0 * Tq * DMq;
        __nv_bfloat16*  ol_   = ol   + b0 * Tq * DMq;
        unsigned*       qk_   = qkvp + b0 * Tq * 3 * DMq;
        __nv_bfloat16*  hh_   = hh   + b0 * Tq * DMq;
        __nv_bfloat16*  hl_   = hl   + b0 * Tq * DMq;
        float*          of_   = (float*)d_out + b0 * NCq * Tq;

        const dim3 thr(256);
        const dim3 g_xp (Tq / 32, DINq / 32, HB);
        const dim3 g_dm (Tq / 128, DMq / 128, HB);
        const dim3 g_qkv(Tq / 128, 3 * DMq / 128, HB);
        const dim3 g_nc (Tq / 128, (NCq + 127) / 128, HB);
        const int  g_at = (HB * Tq * 64) / 256;

        xpose_kernel<<<g_xp, thr, 0, S>>>(x_, xh_, xl_);

        gemm_mma<1, DINq, DMq, DMq><<<g_dm, thr, SMEM_TOT, S>>>(
            wh + W_B0, wl + W_B0, xh_, xl_, b0b, nullptr, nullptr, nullptr,
            oh_, ol_, nullptr);

        for (int l = 0; l < 5; l++) {
            const float* bb = (const float*)d_in[4 + 5 * l + 4];
            const int wqkv = W_L0 + l * W_PERL;
            const int bw   = wqkv + 3 * 65536;

            gemm_mma<0, DMq, 3 * DMq, 3 * DMq><<<g_qkv, thr, SMEM_TOT, S>>>(
                wh + wqkv, wl + wqkv, oh_, ol_, nullptr, nullptr, nullptr, nullptr,
                (__nv_bfloat16*)qk_, nullptr, nullptr);

            attn_kernel<<<g_at, thr, 0, S>>>(qk_, hh_, hl_, dils[l]);

            gemm_mma<2, DMq, DMq, DMq><<<g_dm, thr, SMEM_TOT, S>>>(
                wh + bw, wl + bw, hh_, hl_, bb, mask_, oh_, ol_, oh_, ol_, nullptr);
        }

        gemm_mma<3, DMq, NCq, DMq><<<g_nc, thr, SMEM_TOT, S>>>(
            wh + W_B6, wl + W_B6, oh_, ol_, b6b, mask_, nullptr, nullptr,
            nullptr, nullptr, of_);
    }

    // join all streams back into the main stream
    for (int s = 0; s < NSTR; s++) {
        cudaEventRecord(ev_join[s], st[s]);
        cudaStreamWaitEvent(0, ev_join[s], 0);
    }

    cudaEventDestroy(ev_fork);
    for (int s = 0; s < NSTR; s++) {
        cudaEventDestroy(ev_join[s]);
        cudaStreamDestroy(st[s]);
    }
}

// round 12
// speedup vs baseline: 1.9868x; 1.3293x over previous
#include <cuda_runtime.h>
#include <cuda_fp16.h>

#define Bq   8
#define Tq   4096
#define DINq 1024
#define DMq  256
#define NCq  157

// ---------------------------------------------------------------------------
// Activations: single fp16 plane, [B, T, C] (K-major for MMA B operand).
// Weights: fp16 hi + lo planes (W = hi + lo, exact to 2^-24).
// GEMM computes W_hi*B + W_lo*B = W*B exactly on fp16-quantized activations;
// the only error is per-layer fp16 activation quantization (~2^-12).
// ---------------------------------------------------------------------------
__device__ __half g_x  [Bq * Tq * DINq];
__device__ __half g_o  [Bq * Tq * DMq];
__device__ __half g_qkv[Bq * Tq * 3 * DMq];
__device__ __half g_h  [Bq * Tq * DMq];

// Weights: b0w(256x1024), per layer wq|wk|wv|bw (each 256x256), b6w(157x256)
#define W_B0    0
#define W_L0    262144
#define W_PERL  (4 * 65536)
#define W_B6    (262144 + 5 * W_PERL)
#define W_TOTAL (W_B6 + NCq * DMq)
__device__ __half g_wh[W_TOTAL];
__device__ __half g_wl[W_TOTAL];

// ---------------------------------------------------------------------------
// Helpers
// ---------------------------------------------------------------------------
__device__ __forceinline__ unsigned smem_u32(const void* p) {
    unsigned a;
    asm("{ .reg .u64 t; cvta.to.shared.u64 t, %1; cvt.u32.u64 %0, t; }" : "=r"(a) : "l"(p));
    return a;
}
__device__ __forceinline__ void splitw(float v, __half& h, __half& l) {
    h = __float2half_rn(v);
    l = __float2half_rn(v - __half2float(h));
}
__device__ __forceinline__ void ldmat4(unsigned (&r)[4], unsigned addr) {
    asm volatile("ldmatrix.sync.aligned.m8n8.x4.shared.b16 {%0,%1,%2,%3}, [%4];"
                 : "=r"(r[0]), "=r"(r[1]), "=r"(r[2]), "=r"(r[3]) : "r"(addr));
}
__device__ __forceinline__ void mma16816(float (&c)[4], const unsigned (&a)[4],
                                         unsigned b0, unsigned b1) {
    asm volatile(
        "mma.sync.aligned.m16n8k16.row.col.f32.f16.f16.f32 "
        "{%0,%1,%2,%3}, {%4,%5,%6,%7}, {%8,%9}, {%0,%1,%2,%3};"
        : "+f"(c[0]), "+f"(c[1]), "+f"(c[2]), "+f"(c[3])
        : "r"(a[0]), "r"(a[1]), "r"(a[2]), "r"(a[3]), "r"(b0), "r"(b1));
}
// L1-bypass async copy (tiles have zero L1 reuse)
__device__ __forceinline__ void cp16(unsigned saddr, const void* gaddr, int srcsz) {
    asm volatile("cp.async.cg.shared.global [%0], [%1], 16, %2;"
                 :: "r"(saddr), "l"(gaddr), "r"(srcsz) : "memory");
}
#define CP_COMMIT() asm volatile("cp.async.commit_group;" ::: "memory")
#define CP_WAIT1()  asm volatile("cp.async.wait_group 1;" ::: "memory")

// ---------------------------------------------------------------------------
// GEMM: D[o,t] = sum_i W[o,i] * Act[b,t,i]   (split-fp16 x2, mma.sync)
// Block 128(M=o) x 128(N=t), K-chunk 32, 256 threads (8 warps, 4m x 2n),
// warp tile 32x64. cp.async 3-stage pipeline, 64B stride + XOR swizzle.
// Stage: W_hi(8K) | W_lo(8K) | B(8K) = 24KB.
// EPI: 0 plain -> fp16 [b,t,o] stride OSTR      (qkv)
//      1 +bias -> fp16                          (b0)
//      2 (resid+D+bias)*mask -> fp16            (bottleneck)
//      3 (D+bias)*mask -> fp32 [b,o,t]          (final)
// ---------------------------------------------------------------------------
#define TILE_P   8192
#define STAGE    24576
#define SMEM_TOT 73728

template <int EPI, int KTOT, int OROWS, int OSTR>
__global__ void __launch_bounds__(256, 2)
gemm_mma(const __half* __restrict__ Whi, const __half* __restrict__ Wlo,
         const __half* __restrict__ Act,
         const float* __restrict__ bias, const float* __restrict__ mask,
         const __half* __restrict__ Resid,
         __half* __restrict__ Out, float* __restrict__ OF)
{
    extern __shared__ char smem[];
    const unsigned sb = smem_u32(smem);
    const int tid  = threadIdx.x;
    const int lane = tid & 31, wid = tid >> 5;
    const int bT = blockIdx.x * 128;
    const int bO = blockIdx.y * 128;
    const int b  = blockIdx.z;
    const int m0 = (wid & 3) * 32;
    const int n0 = (wid >> 2) * 64;

    constexpr bool GUARDA = (OROWS & 127) != 0;
    constexpr int NCH = KTOT / 32;

    const __half* Bg = Act + ((size_t)b * Tq + bT) * KTOT;

    // ldmatrix per-thread swizzled offsets (64B stride, chunk ^= (row>>1)&3)
    const int raA  = lane & 15;
    const int xorA = (raA >> 1) & 3;
    const int laA[2] = { raA * 64 + ((((lane >> 4)    ) ^ xorA) << 4),
                         raA * 64 + ((((lane >> 4) + 2) ^ xorA) << 4) };
    const int matv = lane >> 3;
    const int rbB  = (lane & 7) + ((matv >> 1) * 8);
    const int xorB = (rbB >> 1) & 3;
    const int lbB[2] = { rbB * 64 + ((((matv & 1)    ) ^ xorB) << 4),
                         rbB * 64 + ((((matv & 1) + 2) ^ xorB) << 4) };

    float acc[2][8][4];
#pragma unroll
    for (int i = 0; i < 2; i++)
#pragma unroll
        for (int j = 0; j < 8; j++)
#pragma unroll
            for (int l = 0; l < 4; l++) acc[i][j][l] = 0.f;

    // ---- async tile issue: 6 cp16/thread (W.hi, W.lo, B) ----
    auto issue = [&](int ch, int stg) {
        if (ch < NCH) {
            const int k0 = ch * 32;
            const unsigned st = sb + stg * STAGE;
#pragma unroll
            for (int i = 0; i < 6; i++) {
                const int task = i * 256 + tid;          // 0..1535
                const int plane = task >> 9;             // 0=W.hi 1=W.lo 2=B
                const int q = task & 511;
                const int row = q >> 2, c = q & 3;
                const unsigned soff = (unsigned)(row * 64 + ((c ^ ((row >> 1) & 3)) << 4));
                if (plane < 2) {
                    int asz = 16;
                    size_t aoff = (size_t)(bO + row) * KTOT + k0 + c * 8;
                    if (GUARDA && (bO + row >= OROWS)) { asz = 0; aoff = 0; }
                    cp16(st + plane * TILE_P + soff, (plane ? Wlo : Whi) + aoff, asz);
                } else {
                    cp16(st + 2 * TILE_P + soff,
                         Bg + (size_t)row * KTOT + k0 + c * 8, 16);
                }
            }
        }
        CP_COMMIT();
    };

    issue(0, 0);
    issue(1, 1);

    int cs = 0, is = 2;
#pragma unroll 1
    for (int ch = 0; ch < NCH; ch++) {
        CP_WAIT1();
        __syncthreads();
        issue(ch + 2, is);
        is = (is == 2) ? 0 : is + 1;

        const unsigned A0_ = sb + cs * STAGE;
        const unsigned A1_ = A0_ + TILE_P;
        const unsigned B_  = A0_ + 2 * TILE_P;
        cs = (cs == 2) ? 0 : cs + 1;

#pragma unroll
        for (int kk = 0; kk < 2; kk++) {
            unsigned ah[2][4], al[2][4];
            ldmat4(ah[0], A0_ + (m0     ) * 64 + laA[kk]);
            ldmat4(ah[1], A0_ + (m0 + 16) * 64 + laA[kk]);
            ldmat4(al[0], A1_ + (m0     ) * 64 + laA[kk]);
            ldmat4(al[1], A1_ + (m0 + 16) * 64 + laA[kk]);
#pragma unroll
            for (int nt2 = 0; nt2 < 4; nt2++) {
                unsigned bu[4];
                ldmat4(bu, B_ + (n0 + nt2 * 16) * 64 + lbB[kk]);
                // W_hi * B
                mma16816(acc[0][nt2 * 2 + 0], ah[0], bu[0], bu[1]);
                mma16816(acc[0][nt2 * 2 + 1], ah[0], bu[2], bu[3]);
                mma16816(acc[1][nt2 * 2 + 0], ah[1], bu[0], bu[1]);
                mma16816(acc[1][nt2 * 2 + 1], ah[1], bu[2], bu[3]);
                // W_lo * B
                mma16816(acc[0][nt2 * 2 + 0], al[0], bu[0], bu[1]);
                mma16816(acc[0][nt2 * 2 + 1], al[0], bu[2], bu[3]);
                mma16816(acc[1][nt2 * 2 + 0], al[1], bu[0], bu[1]);
                mma16816(acc[1][nt2 * 2 + 1], al[1], bu[2], bu[3]);
            }
        }
    }

    // ---- epilogue ----
    const int g = lane >> 2, tig = lane & 3;
#pragma unroll
    for (int mi = 0; mi < 2; mi++) {
#pragma unroll
        for (int pr = 0; pr < 2; pr++) {
            const int o = bO + m0 + mi * 16 + g + pr * 8;
            float bs = 0.f;
            if (EPI >= 1) bs = (!GUARDA || o < OROWS) ? bias[o] : 0.f;
#pragma unroll
            for (int nt = 0; nt < 8; nt++) {
                const int t = bT + n0 + nt * 8 + 2 * tig;
                float v0 = acc[mi][nt][pr * 2 + 0] + bs;
                float v1 = acc[mi][nt][pr * 2 + 1] + bs;
                if (EPI == 3) {
                    if (!GUARDA || o < OROWS) {
                        const float mk0 = mask[(size_t)b * Tq + t];
                        const float mk1 = mask[(size_t)b * Tq + t + 1];
                        *(float2*)(OF + ((size_t)b * OROWS + o) * Tq + t) =
                            make_float2(v0 * mk0, v1 * mk1);
                    }
                } else {
                    const size_t i0 = ((size_t)b * Tq + t) * OSTR + o;
                    if (EPI == 2) {
                        const float mk0 = mask[(size_t)b * Tq + t];
                        const float mk1 = mask[(size_t)b * Tq + t + 1];
                        v0 = (__half2float(Resid[i0])        + v0) * mk0;
                        v1 = (__half2float(Resid[i0 + OSTR]) + v1) * mk1;
                    }
                    Out[i0]        = __float2half_rn(v0);
                    Out[i0 + OSTR] = __float2half_rn(v1);
                }
            }
        }
    }
}

// ---------------------------------------------------------------------------
// x transpose: [B, DIN, T] fp32 -> [B, T, DIN] fp16
// ---------------------------------------------------------------------------
__global__ __launch_bounds__(256)
void xpose_kernel(const float* __restrict__ x, __half* __restrict__ xo)
{
    __shared__ float s[32][33];
    const int t0 = blockIdx.x * 32, i0 = blockIdx.y * 32, b = blockIdx.z;
    const int tx = threadIdx.x & 31, ty = threadIdx.x >> 5;
    const float* xb = x + (size_t)b * DINq * Tq;
#pragma unroll
    for (int kk = 0; kk < 4; kk++)
        s[ty + 8 * kk][tx] = xb[(size_t)(i0 + ty + 8 * kk) * Tq + t0 + tx];
    __syncthreads();
#pragma unroll
    for (int kk = 0; kk < 4; kk++) {
        const size_t idx = ((size_t)b * Tq + t0 + ty + 8 * kk) * DINq + i0 + tx;
        xo[idx] = __float2half_rn(s[tx][ty + 8 * kk]);
    }
}

// ---------------------------------------------------------------------------
// Weight split: 22 fp32 matrices -> fp16 hi/lo
// ---------------------------------------------------------------------------
struct WPtrs { const float* p[22]; };

__global__ __launch_bounds__(256)
void convw_kernel(WPtrs wp, __half* __restrict__ wh, __half* __restrict__ wl)
{
    const int idx = blockIdx.x * 256 + threadIdx.x;
    int off = 0;
#pragma unroll
    for (int m = 0; m < 22; m++) {
        const int sz = (m == 0) ? 262144 : ((m == 21) ? NCq * DMq : 65536);
        if (idx < off + sz) {
            __half h, l;
            splitw(wp.p[m][idx - off], h, l);
            wh[idx] = h; wl[idx] = l;
            return;
        }
        off += sz;
    }
}

// ---------------------------------------------------------------------------
// Dilated 3-tap softmax attention + ReLU on fp16 qkv [B,T,768]
// ---------------------------------------------------------------------------
__device__ __forceinline__ void load4h(const __half* __restrict__ p, size_t e, float (&o)[4])
{
    const __half2 a = *(const __half2*)(p + e);
    const __half2 c = *(const __half2*)(p + e + 2);
    o[0] = __low2float(a); o[1] = __high2float(a);
    o[2] = __low2float(c); o[3] = __high2float(c);
}

__device__ __forceinline__ float attn1(float q, float k0, float k1, float k2,
                                       float v0, float v1, float v2)
{
    const float s0 = q * k0, s1 = q * k1, s2 = q * k2;
    const float mx = fmaxf(s0, fmaxf(s1, s2));
    const float e0 = __expf(s0 - mx), e1 = __expf(s1 - mx), e2 = __expf(s2 - mx);
    return fmaxf((e0 * v0 + e1 * v1 + e2 * v2) / (e0 + e1 + e2), 0.f);
}

__global__ __launch_bounds__(256)
void attn_kernel(const __half* __restrict__ qkv, __half* __restrict__ hout, int d)
{
    const size_t gid = (size_t)blockIdx.x * 256 + threadIdx.x;
    const int c4 = (int)(gid & 63);
    const int t  = (int)((gid >> 6) & (Tq - 1));
    const int b  = (int)(gid >> 18);
    const size_t rq = ((size_t)b * Tq + t) * 768 + c4 * 4;
    const long long off = (long long)d * 768;

    float q[4], k1[4], v1[4];
    load4h(qkv, rq,       q);
    load4h(qkv, rq + 256, k1);
    load4h(qkv, rq + 512, v1);
    float k0[4] = {0, 0, 0, 0}, v0[4] = {0, 0, 0, 0};
    float k2[4] = {0, 0, 0, 0}, v2[4] = {0, 0, 0, 0};
    if (t - d >= 0) { load4h(qkv, rq + 256 - off, k0); load4h(qkv, rq + 512 - off, v0); }
    if (t + d < Tq) { load4h(qkv, rq + 256 + off, k2); load4h(qkv, rq + 512 + off, v2); }

    const size_t e = ((size_t)b * Tq + t) * DMq + c4 * 4;
    const __half2 p0 = __floats2half2_rn(
        attn1(q[0], k0[0], k1[0], k2[0], v0[0], v1[0], v2[0]),
        attn1(q[1], k0[1], k1[1], k2[1], v0[1], v1[1], v2[1]));
    const __half2 p1 = __floats2half2_rn(
        attn1(q[2], k0[2], k1[2], k2[2], v0[2], v1[2], v2[2]),
        attn1(q[3], k0[3], k1[3], k2[3], v0[3], v1[3], v2[3]));
    uint2 w;
    w.x = *(const unsigned*)&p0;
    w.y = *(const unsigned*)&p1;
    *(uint2*)(hout + e) = w;
}

// ---------------------------------------------------------------------------
// Launch: batch split B=8 -> 4 streams x 2 batches (fork-join capture pattern)
// ---------------------------------------------------------------------------
#define NSTR 4

extern "C" void kernel_launch(void* const* d_in, const int* in_sizes, int n_in,
                              void* d_out, int out_size)
{
    const float* x    = (const float*)d_in[0];
    const float* mask = (const float*)d_in[1];
    const float* b0b  = (const float*)d_in[3];
    const float* b6b  = (const float*)d_in[30];

    __half *xb, *ob, *qkvb, *hb, *wh, *wl;
    cudaGetSymbolAddress((void**)&xb,   g_x);
    cudaGetSymbolAddress((void**)&ob,   g_o);
    cudaGetSymbolAddress((void**)&qkvb, g_qkv);
    cudaGetSymbolAddress((void**)&hb,   g_h);
    cudaGetSymbolAddress((void**)&wh,   g_wh);
    cudaGetSymbolAddress((void**)&wl,   g_wl);

    cudaFuncSetAttribute(gemm_mma<1, DINq, DMq, DMq>,        cudaFuncAttributeMaxDynamicSharedMemorySize, SMEM_TOT);
    cudaFuncSetAttribute(gemm_mma<0, DMq, 3 * DMq, 3 * DMq>, cudaFuncAttributeMaxDynamicSharedMemorySize, SMEM_TOT);
    cudaFuncSetAttribute(gemm_mma<2, DMq, DMq, DMq>,         cudaFuncAttributeMaxDynamicSharedMemorySize, SMEM_TOT);
    cudaFuncSetAttribute(gemm_mma<3, DMq, NCq, DMq>,         cudaFuncAttributeMaxDynamicSharedMemorySize, SMEM_TOT);

    // split weights (shared by all streams)
    WPtrs wp;
    wp.p[0] = (const float*)d_in[2];
    for (int l = 0; l < 5; l++) {
        wp.p[1 + 4 * l + 0] = (const float*)d_in[4 + 5 * l + 0];
        wp.p[1 + 4 * l + 1] = (const float*)d_in[4 + 5 * l + 1];
        wp.p[1 + 4 * l + 2] = (const float*)d_in[4 + 5 * l + 2];
        wp.p[1 + 4 * l + 3] = (const float*)d_in[4 + 5 * l + 3];
    }
    wp.p[21] = (const float*)d_in[29];
    convw_kernel<<<W_TOTAL / 256, 256>>>(wp, wh, wl);

    // fork worker streams off the main (capture) stream
    cudaStream_t st[NSTR];
    cudaEvent_t ev_fork, ev_join[NSTR];
    for (int s = 0; s < NSTR; s++) cudaStreamCreateWithFlags(&st[s], cudaStreamNonBlocking);
    cudaEventCreateWithFlags(&ev_fork, cudaEventDisableTiming);
    for (int s = 0; s < NSTR; s++) cudaEventCreateWithFlags(&ev_join[s], cudaEventDisableTiming);
    cudaEventRecord(ev_fork, 0);
    for (int s = 0; s < NSTR; s++) cudaStreamWaitEvent(st[s], ev_fork, 0);

    const int dils[5] = {1, 2, 4, 8, 16};
    const int HB = Bq / NSTR;   // 2 batches per stream

    for (int s = 0; s < NSTR; s++) {
        cudaStream_t S = st[s];
        const size_t b0 = (size_t)s * HB;

        const float* x_    = x    + b0 * DINq * Tq;
        const float* mask_ = mask + b0 * Tq;
        __half*      xb_   = xb   + b0 * Tq * DINq;
        __half*      ob_   = ob   + b0 * Tq * DMq;
        __half*      qk_   = qkvb + b0 * Tq * 3 * DMq;
        __half*      hb_   = hb   + b0 * Tq * DMq;
        float*       of_   = (float*)d_out + b0 * NCq * Tq;

        const dim3 thr(256);
        const dim3 g_xp (Tq / 32, DINq / 32, HB);
        const dim3 g_dm (Tq / 128, DMq / 128, HB);
        const dim3 g_qkv(Tq / 128, 3 * DMq / 128, HB);
        const dim3 g_nc (Tq / 128, (NCq + 127) / 128, HB);
        const int  g_at = (HB * Tq * 64) / 256;

        xpose_kernel<<<g_xp, thr, 0, S>>>(x_, xb_);

        gemm_mma<1, DINq, DMq, DMq><<<g_dm, thr, SMEM_TOT, S>>>(
            wh + W_B0, wl + W_B0, xb_, b0b, nullptr, nullptr, ob_, nullptr);

        for (int l = 0; l < 5; l++) {
            const float* bb = (const float*)d_in[4 + 5 * l + 4];
            const int wqkv = W_L0 + l * W_PERL;
            const int bw   = wqkv + 3 * 65536;

            gemm_mma<0, DMq, 3 * DMq, 3 * DMq><<<g_qkv, thr, SMEM_TOT, S>>>(
                wh + wqkv, wl + wqkv, ob_, nullptr, nullptr, nullptr, qk_, nullptr);

            attn_kernel<<<g_at, thr, 0, S>>>(qk_, hb_, dils[l]);

            gemm_mma<2, DMq, DMq, DMq><<<g_dm, thr, SMEM_TOT, S>>>(
                wh + bw, wl + bw, hb_, bb, mask_, ob_, ob_, nullptr);
        }

        gemm_mma<3, DMq, NCq, DMq><<<g_nc, thr, SMEM_TOT, S>>>(
            wh + W_B6, wl + W_B6, ob_, b6b, mask_, nullptr, nullptr, of_);
    }

    // join all streams back into the main stream
    for (int s = 0; s < NSTR; s++) {
        cudaEventRecord(ev_join[s], st[s]);
        cudaStreamWaitEvent(0, ev_join[s], 0);
    }

    cudaEventDestroy(ev_fork);
    for (int s = 0; s < NSTR; s++) {
        cudaEventDestroy(ev_join[s]);
        cudaStreamDestroy(st[s]);
    }
}

// round 13
// speedup vs baseline: 2.0203x; 1.0168x over previous
#include <cuda_runtime.h>
#include <cuda_fp16.h>

#define Bq   8
#define Tq   4096
#define DINq 1024
#define DMq  256
#define NCq  157

// ---------------------------------------------------------------------------
// Activations: single fp16 plane, [B, T, C] (K-major for MMA B operand).
// Weights: fp16 hi + lo planes (W = hi + lo, exact to 2^-24).
// GEMM computes W_hi*B + W_lo*B = W*B exactly on fp16-quantized activations.
// ---------------------------------------------------------------------------
__device__ __half g_x  [Bq * Tq * DINq];
__device__ __half g_o  [Bq * Tq * DMq];
__device__ __half g_qkv[Bq * Tq * 3 * DMq];
__device__ __half g_h  [Bq * Tq * DMq];

// Weights: b0w(256x1024), per layer wq|wk|wv|bw (each 256x256), b6w(157x256)
#define W_B0    0
#define W_L0    262144
#define W_PERL  (4 * 65536)
#define W_B6    (262144 + 5 * W_PERL)
#define W_TOTAL (W_B6 + NCq * DMq)
__device__ __half g_wh[W_TOTAL];
__device__ __half g_wl[W_TOTAL];

// ---------------------------------------------------------------------------
// Helpers
// ---------------------------------------------------------------------------
__device__ __forceinline__ unsigned smem_u32(const void* p) {
    unsigned a;
    asm("{ .reg .u64 t; cvta.to.shared.u64 t, %1; cvt.u32.u64 %0, t; }" : "=r"(a) : "l"(p));
    return a;
}
__device__ __forceinline__ void splitw(float v, __half& h, __half& l) {
    h = __float2half_rn(v);
    l = __float2half_rn(v - __half2float(h));
}
__device__ __forceinline__ void ldmat4(unsigned (&r)[4], unsigned addr) {
    asm volatile("ldmatrix.sync.aligned.m8n8.x4.shared.b16 {%0,%1,%2,%3}, [%4];"
                 : "=r"(r[0]), "=r"(r[1]), "=r"(r[2]), "=r"(r[3]) : "r"(addr));
}
__device__ __forceinline__ void mma16816(float (&c)[4], const unsigned (&a)[4],
                                         unsigned b0, unsigned b1) {
    asm volatile(
        "mma.sync.aligned.m16n8k16.row.col.f32.f16.f16.f32 "
        "{%0,%1,%2,%3}, {%4,%5,%6,%7}, {%8,%9}, {%0,%1,%2,%3};"
        : "+f"(c[0]), "+f"(c[1]), "+f"(c[2]), "+f"(c[3])
        : "r"(a[0]), "r"(a[1]), "r"(a[2]), "r"(a[3]), "r"(b0), "r"(b1));
}
// L1-bypass async copy (tiles have zero L1 reuse)
__device__ __forceinline__ void cp16(unsigned saddr, const void* gaddr, int srcsz) {
    asm volatile("cp.async.cg.shared.global [%0], [%1], 16, %2;"
                 :: "r"(saddr), "l"(gaddr), "r"(srcsz) : "memory");
}
#define CP_COMMIT() asm volatile("cp.async.commit_group;" ::: "memory")
#define CP_WAIT2()  asm volatile("cp.async.wait_group 2;" ::: "memory")

// ---------------------------------------------------------------------------
// GEMM: D[o,t] = sum_i W[o,i] * Act[b,t,i]   (split-fp16 x2, mma.sync)
// Block 128(M=o) x 128(N=t), K-chunk 32, 256 threads (8 warps, 4m x 2n),
// warp tile 32x64. cp.async 4-stage pipeline (wait_group 2),
// 64B stride + XOR swizzle.  Stage: W_hi(8K) | W_lo(8K) | B(8K) = 24KB.
// EPI: 0 plain -> fp16 [b,t,o] stride OSTR      (qkv)
//      1 +bias -> fp16                          (b0)
//      2 (resid+D+bias)*mask -> fp16            (bottleneck)
//      3 (D+bias)*mask -> fp32 [b,o,t]          (final)
// ---------------------------------------------------------------------------
#define TILE_P   8192
#define STAGE    24576
#define SMEM_TOT 98304              // 4 stages

template <int EPI, int KTOT, int OROWS, int OSTR>
__global__ void __launch_bounds__(256, 2)
gemm_mma(const __half* __restrict__ Whi, const __half* __restrict__ Wlo,
         const __half* __restrict__ Act,
         const float* __restrict__ bias, const float* __restrict__ mask,
         const __half* __restrict__ Resid,
         __half* __restrict__ Out, float* __restrict__ OF)
{
    extern __shared__ char smem[];
    const unsigned sb = smem_u32(smem);
    const int tid  = threadIdx.x;
    const int lane = tid & 31, wid = tid >> 5;
    const int bT = blockIdx.x * 128;
    const int bO = blockIdx.y * 128;
    const int b  = blockIdx.z;
    const int m0 = (wid & 3) * 32;
    const int n0 = (wid >> 2) * 64;

    constexpr bool GUARDA = (OROWS & 127) != 0;
    constexpr int NCH = KTOT / 32;

    const __half* Bg = Act + ((size_t)b * Tq + bT) * KTOT;

    // ldmatrix per-thread swizzled offsets (64B stride, chunk ^= (row>>1)&3)
    const int raA  = lane & 15;
    const int xorA = (raA >> 1) & 3;
    const int laA[2] = { raA * 64 + ((((lane >> 4)    ) ^ xorA) << 4),
                         raA * 64 + ((((lane >> 4) + 2) ^ xorA) << 4) };
    const int matv = lane >> 3;
    const int rbB  = (lane & 7) + ((matv >> 1) * 8);
    const int xorB = (rbB >> 1) & 3;
    const int lbB[2] = { rbB * 64 + ((((matv & 1)    ) ^ xorB) << 4),
                         rbB * 64 + ((((matv & 1) + 2) ^ xorB) << 4) };

    float acc[2][8][4];
#pragma unroll
    for (int i = 0; i < 2; i++)
#pragma unroll
        for (int j = 0; j < 8; j++)
#pragma unroll
            for (int l = 0; l < 4; l++) acc[i][j][l] = 0.f;

    // ---- async tile issue: 6 cp16/thread (W.hi, W.lo, B) ----
    auto issue = [&](int ch, int stg) {
        if (ch < NCH) {
            const int k0 = ch * 32;
            const unsigned st = sb + stg * STAGE;
#pragma unroll
            for (int i = 0; i < 6; i++) {
                const int task = i * 256 + tid;          // 0..1535
                const int plane = task >> 9;             // 0=W.hi 1=W.lo 2=B
                const int q = task & 511;
                const int row = q >> 2, c = q & 3;
                const unsigned soff = (unsigned)(row * 64 + ((c ^ ((row >> 1) & 3)) << 4));
                if (plane < 2) {
                    int asz = 16;
                    size_t aoff = (size_t)(bO + row) * KTOT + k0 + c * 8;
                    if (GUARDA && (bO + row >= OROWS)) { asz = 0; aoff = 0; }
                    cp16(st + plane * TILE_P + soff, (plane ? Wlo : Whi) + aoff, asz);
                } else {
                    cp16(st + 2 * TILE_P + soff,
                         Bg + (size_t)row * KTOT + k0 + c * 8, 16);
                }
            }
        }
        CP_COMMIT();
    };

    issue(0, 0);
    issue(1, 1);
    issue(2, 2);

    int cs = 0, is = 3;
#pragma unroll 1
    for (int ch = 0; ch < NCH; ch++) {
        CP_WAIT2();
        __syncthreads();
        issue(ch + 3, is);
        is = (is + 1) & 3;

        const unsigned A0_ = sb + cs * STAGE;
        const unsigned A1_ = A0_ + TILE_P;
        const unsigned B_  = A0_ + 2 * TILE_P;
        cs = (cs + 1) & 3;

#pragma unroll
        for (int kk = 0; kk < 2; kk++) {
            unsigned ah[2][4], al[2][4];
            ldmat4(ah[0], A0_ + (m0     ) * 64 + laA[kk]);
            ldmat4(ah[1], A0_ + (m0 + 16) * 64 + laA[kk]);
            ldmat4(al[0], A1_ + (m0     ) * 64 + laA[kk]);
            ldmat4(al[1], A1_ + (m0 + 16) * 64 + laA[kk]);
#pragma unroll
            for (int nt2 = 0; nt2 < 4; nt2++) {
                unsigned bu[4];
                ldmat4(bu, B_ + (n0 + nt2 * 16) * 64 + lbB[kk]);
                // W_hi * B
                mma16816(acc[0][nt2 * 2 + 0], ah[0], bu[0], bu[1]);
                mma16816(acc[0][nt2 * 2 + 1], ah[0], bu[2], bu[3]);
                mma16816(acc[1][nt2 * 2 + 0], ah[1], bu[0], bu[1]);
                mma16816(acc[1][nt2 * 2 + 1], ah[1], bu[2], bu[3]);
                // W_lo * B
                mma16816(acc[0][nt2 * 2 + 0], al[0], bu[0], bu[1]);
                mma16816(acc[0][nt2 * 2 + 1], al[0], bu[2], bu[3]);
                mma16816(acc[1][nt2 * 2 + 0], al[1], bu[0], bu[1]);
                mma16816(acc[1][nt2 * 2 + 1], al[1], bu[2], bu[3]);
            }
        }
    }

    // ---- epilogue ----
    const int g = lane >> 2, tig = lane & 3;
#pragma unroll
    for (int mi = 0; mi < 2; mi++) {
#pragma unroll
        for (int pr = 0; pr < 2; pr++) {
            const int o = bO + m0 + mi * 16 + g + pr * 8;
            float bs = 0.f;
            if (EPI >= 1) bs = (!GUARDA || o < OROWS) ? bias[o] : 0.f;
#pragma unroll
            for (int nt = 0; nt < 8; nt++) {
                const int t = bT + n0 + nt * 8 + 2 * tig;
                float v0 = acc[mi][nt][pr * 2 + 0] + bs;
                float v1 = acc[mi][nt][pr * 2 + 1] + bs;
                if (EPI == 3) {
                    if (!GUARDA || o < OROWS) {
                        const float mk0 = mask[(size_t)b * Tq + t];
                        const float mk1 = mask[(size_t)b * Tq + t + 1];
                        *(float2*)(OF + ((size_t)b * OROWS + o) * Tq + t) =
                            make_float2(v0 * mk0, v1 * mk1);
                    }
                } else {
                    const size_t i0 = ((size_t)b * Tq + t) * OSTR + o;
                    if (EPI == 2) {
                        const float mk0 = mask[(size_t)b * Tq + t];
                        const float mk1 = mask[(size_t)b * Tq + t + 1];
                        v0 = (__half2float(Resid[i0])        + v0) * mk0;
                        v1 = (__half2float(Resid[i0 + OSTR]) + v1) * mk1;
                    }
                    Out[i0]        = __float2half_rn(v0);
                    Out[i0 + OSTR] = __float2half_rn(v1);
                }
            }
        }
    }
}

// ---------------------------------------------------------------------------
// x transpose: [B, DIN, T] fp32 -> [B, T, DIN] fp16
// ---------------------------------------------------------------------------
__global__ __launch_bounds__(256)
void xpose_kernel(const float* __restrict__ x, __half* __restrict__ xo)
{
    __shared__ float s[32][33];
    const int t0 = blockIdx.x * 32, i0 = blockIdx.y * 32, b = blockIdx.z;
    const int tx = threadIdx.x & 31, ty = threadIdx.x >> 5;
    const float* xb = x + (size_t)b * DINq * Tq;
#pragma unroll
    for (int kk = 0; kk < 4; kk++)
        s[ty + 8 * kk][tx] = xb[(size_t)(i0 + ty + 8 * kk) * Tq + t0 + tx];
    __syncthreads();
#pragma unroll
    for (int kk = 0; kk < 4; kk++) {
        const size_t idx = ((size_t)b * Tq + t0 + ty + 8 * kk) * DINq + i0 + tx;
        xo[idx] = __float2half_rn(s[tx][ty + 8 * kk]);
    }
}

// ---------------------------------------------------------------------------
// Weight split: 22 fp32 matrices -> fp16 hi/lo
// ---------------------------------------------------------------------------
struct WPtrs { const float* p[22]; };

__global__ __launch_bounds__(256)
void convw_kernel(WPtrs wp, __half* __restrict__ wh, __half* __restrict__ wl)
{
    const int idx = blockIdx.x * 256 + threadIdx.x;
    int off = 0;
#pragma unroll
    for (int m = 0; m < 22; m++) {
        const int sz = (m == 0) ? 262144 : ((m == 21) ? NCq * DMq : 65536);
        if (idx < off + sz) {
            __half h, l;
            splitw(wp.p[m][idx - off], h, l);
            wh[idx] = h; wl[idx] = l;
            return;
        }
        off += sz;
    }
}

// ---------------------------------------------------------------------------
// Dilated 3-tap softmax attention + ReLU on fp16 qkv [B,T,768]
// ---------------------------------------------------------------------------
__device__ __forceinline__ void load4h(const __half* __restrict__ p, size_t e, float (&o)[4])
{
    const __half2 a = *(const __half2*)(p + e);
    const __half2 c = *(const __half2*)(p + e + 2);
    o[0] = __low2float(a); o[1] = __high2float(a);
    o[2] = __low2float(c); o[3] = __high2float(c);
}

__device__ __forceinline__ float attn1(float q, float k0, float k1, float k2,
                                       float v0, float v1, float v2)
{
    const float s0 = q * k0, s1 = q * k1, s2 = q * k2;
    const float mx = fmaxf(s0, fmaxf(s1, s2));
    const float e0 = __expf(s0 - mx), e1 = __expf(s1 - mx), e2 = __expf(s2 - mx);
    return fmaxf((e0 * v0 + e1 * v1 + e2 * v2) / (e0 + e1 + e2), 0.f);
}

__global__ __launch_bounds__(256)
void attn_kernel(const __half* __restrict__ qkv, __half* __restrict__ hout, int d)
{
    const size_t gid = (size_t)blockIdx.x * 256 + threadIdx.x;
    const int c4 = (int)(gid & 63);
    const int t  = (int)((gid >> 6) & (Tq - 1));
    const int b  = (int)(gid >> 18);
    const size_t rq = ((size_t)b * Tq + t) * 768 + c4 * 4;
    const long long off = (long long)d * 768;

    float q[4], k1[4], v1[4];
    load4h(qkv, rq,       q);
    load4h(qkv, rq + 256, k1);
    load4h(qkv, rq + 512, v1);
    float k0[4] = {0, 0, 0, 0}, v0[4] = {0, 0, 0, 0};
    float k2[4] = {0, 0, 0, 0}, v2[4] = {0, 0, 0, 0};
    if (t - d >= 0) { load4h(qkv, rq + 256 - off, k0); load4h(qkv, rq + 512 - off, v0); }
    if (t + d < Tq) { load4h(qkv, rq + 256 + off, k2); load4h(qkv, rq + 512 + off, v2); }

    const size_t e = ((size_t)b * Tq + t) * DMq + c4 * 4;
    const __half2 p0 = __floats2half2_rn(
        attn1(q[0], k0[0], k1[0], k2[0], v0[0], v1[0], v2[0]),
        attn1(q[1], k0[1], k1[1], k2[1], v0[1], v1[1], v2[1]));
    const __half2 p1 = __floats2half2_rn(
        attn1(q[2], k0[2], k1[2], k2[2], v0[2], v1[2], v2[2]),
        attn1(q[3], k0[3], k1[3], k2[3], v0[3], v1[3], v2[3]));
    uint2 w;
    w.x = *(const unsigned*)&p0;
    w.y = *(const unsigned*)&p1;
    *(uint2*)(hout + e) = w;
}

// ---------------------------------------------------------------------------
// Launch: batch split B=8 -> 4 streams x 2 batches (fork-join capture pattern)
// ---------------------------------------------------------------------------
#define NSTR 4

extern "C" void kernel_launch(void* const* d_in, const int* in_sizes, int n_in,
                              void* d_out, int out_size)
{
    const float* x    = (const float*)d_in[0];
    const float* mask = (const float*)d_in[1];
    const float* b0b  = (const float*)d_in[3];
    const float* b6b  = (const float*)d_in[30];

    __half *xb, *ob, *qkvb, *hb, *wh, *wl;
    cudaGetSymbolAddress((void**)&xb,   g_x);
    cudaGetSymbolAddress((void**)&ob,   g_o);
    cudaGetSymbolAddress((void**)&qkvb, g_qkv);
    cudaGetSymbolAddress((void**)&hb,   g_h);
    cudaGetSymbolAddress((void**)&wh,   g_wh);
    cudaGetSymbolAddress((void**)&wl,   g_wl);

    cudaFuncSetAttribute(gemm_mma<1, DINq, DMq, DMq>,        cudaFuncAttributeMaxDynamicSharedMemorySize, SMEM_TOT);
    cudaFuncSetAttribute(gemm_mma<0, DMq, 3 * DMq, 3 * DMq>, cudaFuncAttributeMaxDynamicSharedMemorySize, SMEM_TOT);
    cudaFuncSetAttribute(gemm_mma<2, DMq, DMq, DMq>,         cudaFuncAttributeMaxDynamicSharedMemorySize, SMEM_TOT);
    cudaFuncSetAttribute(gemm_mma<3, DMq, NCq, DMq>,         cudaFuncAttributeMaxDynamicSharedMemorySize, SMEM_TOT);

    // split weights (shared by all streams)
    WPtrs wp;
    wp.p[0] = (const float*)d_in[2];
    for (int l = 0; l < 5; l++) {
        wp.p[1 + 4 * l + 0] = (const float*)d_in[4 + 5 * l + 0];
        wp.p[1 + 4 * l + 1] = (const float*)d_in[4 + 5 * l + 1];
        wp.p[1 + 4 * l + 2] = (const float*)d_in[4 + 5 * l + 2];
        wp.p[1 + 4 * l + 3] = (const float*)d_in[4 + 5 * l + 3];
    }
    wp.p[21] = (const float*)d_in[29];
    convw_kernel<<<W_TOTAL / 256, 256>>>(wp, wh, wl);

    // fork worker streams off the main (capture) stream
    cudaStream_t st[NSTR];
    cudaEvent_t ev_fork, ev_join[NSTR];
    for (int s = 0; s < NSTR; s++) cudaStreamCreateWithFlags(&st[s], cudaStreamNonBlocking);
    cudaEventCreateWithFlags(&ev_fork, cudaEventDisableTiming);
    for (int s = 0; s < NSTR; s++) cudaEventCreateWithFlags(&ev_join[s], cudaEventDisableTiming);
    cudaEventRecord(ev_fork, 0);
    for (int s = 0; s < NSTR; s++) cudaStreamWaitEvent(st[s], ev_fork, 0);

    const int dils[5] = {1, 2, 4, 8, 16};
    const int HB = Bq / NSTR;   // 2 batches per stream

    for (int s = 0; s < NSTR; s++) {
        cudaStream_t S = st[s];
        const size_t b0 = (size_t)s * HB;

        const float* x_    = x    + b0 * DINq * Tq;
        const float* mask_ = mask + b0 * Tq;
        __half*      xb_   = xb   + b0 * Tq * DINq;
        __half*      ob_   = ob   + b0 * Tq * DMq;
        __half*      qk_   = qkvb + b0 * Tq * 3 * DMq;
        __half*      hb_   = hb   + b0 * Tq * DMq;
        float*       of_   = (float*)d_out + b0 * NCq * Tq;

        const dim3 thr(256);
        const dim3 g_xp (Tq / 32, DINq / 32, HB);
        const dim3 g_dm (Tq / 128, DMq / 128, HB);
        const dim3 g_qkv(Tq / 128, 3 * DMq / 128, HB);
        const dim3 g_nc (Tq / 128, (NCq + 127) / 128, HB);
        const int  g_at = (HB * Tq * 64) / 256;

        xpose_kernel<<<g_xp, thr, 0, S>>>(x_, xb_);

        gemm_mma<1, DINq, DMq, DMq><<<g_dm, thr, SMEM_TOT, S>>>(
            wh + W_B0, wl + W_B0, xb_, b0b, nullptr, nullptr, ob_, nullptr);

        for (int l = 0; l < 5; l++) {
            const float* bb = (const float*)d_in[4 + 5 * l + 4];
            const int wqkv = W_L0 + l * W_PERL;
            const int bw   = wqkv + 3 * 65536;

            gemm_mma<0, DMq, 3 * DMq, 3 * DMq><<<g_qkv, thr, SMEM_TOT, S>>>(
                wh + wqkv, wl + wqkv, ob_, nullptr, nullptr, nullptr, qk_, nullptr);

            attn_kernel<<<g_at, thr, 0, S>>>(qk_, hb_, dils[l]);

            gemm_mma<2, DMq, DMq, DMq><<<g_dm, thr, SMEM_TOT, S>>>(
                wh + bw, wl + bw, hb_, bb, mask_, ob_, ob_, nullptr);
        }

        gemm_mma<3, DMq, NCq, DMq><<<g_nc, thr, SMEM_TOT, S>>>(
            wh + W_B6, wl + W_B6, ob_, b6b, mask_, nullptr, nullptr, of_);
    }

    // join all streams back into the main stream
    for (int s = 0; s < NSTR; s++) {
        cudaEventRecord(ev_join[s], st[s]);
        cudaStreamWaitEvent(0, ev_join[s], 0);
    }

    cudaEventDestroy(ev_fork);
    for (int s = 0; s < NSTR; s++) {
        cudaEventDestroy(ev_join[s]);
        cudaStreamDestroy(st[s]);
    }
}

// round 14
// speedup vs baseline: 2.0786x; 1.0289x over previous
#include <cuda_runtime.h>
#include <cuda_fp16.h>

#define Bq   8
#define Tq   4096
#define DINq 1024
#define DMq  256
#define NCq  157

// ---------------------------------------------------------------------------
// Activations: single fp16 plane, [B, T, C] (K-major for MMA B operand).
// Weights: fp16 hi + lo planes (W = hi + lo, exact to 2^-24).
// GEMM computes W_hi*B + W_lo*B = W*B exactly on fp16-quantized activations.
// ---------------------------------------------------------------------------
__device__ __half g_x  [Bq * Tq * DINq];
__device__ __half g_o  [Bq * Tq * DMq];
__device__ __half g_qkv[Bq * Tq * 3 * DMq];
__device__ __half g_h  [Bq * Tq * DMq];

// Weights: b0w(256x1024), per layer wq|wk|wv|bw (each 256x256), b6w(157x256)
#define W_B0    0
#define W_L0    262144
#define W_PERL  (4 * 65536)
#define W_B6    (262144 + 5 * W_PERL)
#define W_TOTAL (W_B6 + NCq * DMq)
__device__ __half g_wh[W_TOTAL];
__device__ __half g_wl[W_TOTAL];

// ---------------------------------------------------------------------------
// Helpers
// ---------------------------------------------------------------------------
__device__ __forceinline__ unsigned smem_u32(const void* p) {
    unsigned a;
    asm("{ .reg .u64 t; cvta.to.shared.u64 t, %1; cvt.u32.u64 %0, t; }" : "=r"(a) : "l"(p));
    return a;
}
__device__ __forceinline__ void splitw(float v, __half& h, __half& l) {
    h = __float2half_rn(v);
    l = __float2half_rn(v - __half2float(h));
}
__device__ __forceinline__ void ldmat4(unsigned (&r)[4], unsigned addr) {
    asm volatile("ldmatrix.sync.aligned.m8n8.x4.shared.b16 {%0,%1,%2,%3}, [%4];"
                 : "=r"(r[0]), "=r"(r[1]), "=r"(r[2]), "=r"(r[3]) : "r"(addr));
}
__device__ __forceinline__ void mma16816(float (&c)[4], const unsigned (&a)[4],
                                         unsigned b0, unsigned b1) {
    asm volatile(
        "mma.sync.aligned.m16n8k16.row.col.f32.f16.f16.f32 "
        "{%0,%1,%2,%3}, {%4,%5,%6,%7}, {%8,%9}, {%0,%1,%2,%3};"
        : "+f"(c[0]), "+f"(c[1]), "+f"(c[2]), "+f"(c[3])
        : "r"(a[0]), "r"(a[1]), "r"(a[2]), "r"(a[3]), "r"(b0), "r"(b1));
}
// L1-bypass async copy (tiles have zero L1 reuse)
__device__ __forceinline__ void cp16(unsigned saddr, const void* gaddr, int srcsz) {
    asm volatile("cp.async.cg.shared.global [%0], [%1], 16, %2;"
                 :: "r"(saddr), "l"(gaddr), "r"(srcsz) : "memory");
}
#define CP_COMMIT() asm volatile("cp.async.commit_group;" ::: "memory")
#define CP_WAIT1()  asm volatile("cp.async.wait_group 1;" ::: "memory")

// ---------------------------------------------------------------------------
// GEMM: D[o,t] = sum_i W[o,i] * Act[b,t,i]   (split-fp16 x2, mma.sync)
// Block 128(M=o) x 128(N=t), K-SUPERCHUNK 64, 256 threads (8 warps, 4m x 2n),
// warp tile 32x64. 2 superstages x 48KB, single commit per super,
// 64B stride + XOR swizzle.
// Superstage: W_hi(16K: two 8K k-halves) | W_lo(16K) | B(16K).
// EPI: 0 plain -> fp16 [b,t,o] stride OSTR      (qkv)
//      1 +bias -> fp16                          (b0)
//      2 (resid+D+bias)*mask -> fp16            (bottleneck)
//      3 (D+bias)*mask -> fp32 [b,o,t]          (final)
// ---------------------------------------------------------------------------
#define PART     16384              // one plane per super (two 8K k-halves)
#define SSTAGE   49152              // W_hi | W_lo | B
#define SMEM_TOT 98304              // 2 superstages

template <int EPI, int KTOT, int OROWS, int OSTR>
__global__ void __launch_bounds__(256, 2)
gemm_mma(const __half* __restrict__ Whi, const __half* __restrict__ Wlo,
         const __half* __restrict__ Act,
         const float* __restrict__ bias, const float* __restrict__ mask,
         const __half* __restrict__ Resid,
         __half* __restrict__ Out, float* __restrict__ OF)
{
    extern __shared__ char smem[];
    const unsigned sb = smem_u32(smem);
    const int tid  = threadIdx.x;
    const int lane = tid & 31, wid = tid >> 5;
    const int bT = blockIdx.x * 128;
    const int bO = blockIdx.y * 128;
    const int b  = blockIdx.z;
    const int m0 = (wid & 3) * 32;
    const int n0 = (wid >> 2) * 64;

    constexpr bool GUARDA = (OROWS & 127) != 0;
    constexpr int NSUP = KTOT / 64;

    const __half* Bg = Act + ((size_t)b * Tq + bT) * KTOT;

    // ldmatrix per-thread swizzled offsets (64B stride, chunk ^= (row>>1)&3)
    const int raA  = lane & 15;
    const int xorA = (raA >> 1) & 3;
    const int laA[2] = { raA * 64 + ((((lane >> 4)    ) ^ xorA) << 4),
                         raA * 64 + ((((lane >> 4) + 2) ^ xorA) << 4) };
    const int matv = lane >> 3;
    const int rbB  = (lane & 7) + ((matv >> 1) * 8);
    const int xorB = (rbB >> 1) & 3;
    const int lbB[2] = { rbB * 64 + ((((matv & 1)    ) ^ xorB) << 4),
                         rbB * 64 + ((((matv & 1) + 2) ^ xorB) << 4) };

    float acc[2][8][4];
#pragma unroll
    for (int i = 0; i < 2; i++)
#pragma unroll
        for (int j = 0; j < 8; j++)
#pragma unroll
            for (int l = 0; l < 4; l++) acc[i][j][l] = 0.f;

    // ---- superchunk async issue: 12 cp16/thread, ONE commit group ----
    auto issue = [&](int s, int stg) {
        if (s < NSUP) {
            const int k0 = s * 64;
            const unsigned st = sb + stg * SSTAGE;
#pragma unroll
            for (int i = 0; i < 12; i++) {
                const int task = i * 256 + tid;          // 0..3071
                const int plane = task >> 10;            // 0=W.hi 1=W.lo 2=B
                const int q2 = task & 1023;
                const int kh = q2 >> 9;                  // k-half (0/1)
                const int q  = q2 & 511;
                const int row = q >> 2, c = q & 3;
                const unsigned soff = (unsigned)(plane * PART + kh * 8192 +
                                                 row * 64 + ((c ^ ((row >> 1) & 3)) << 4));
                const int kcol = k0 + kh * 32 + c * 8;
                if (plane < 2) {
                    int asz = 16;
                    size_t aoff = (size_t)(bO + row) * KTOT + kcol;
                    if (GUARDA && (bO + row >= OROWS)) { asz = 0; aoff = 0; }
                    cp16(st + soff, (plane ? Wlo : Whi) + aoff, asz);
                } else {
                    cp16(st + soff, Bg + (size_t)row * KTOT + kcol, 16);
                }
            }
        }
        CP_COMMIT();
    };

    issue(0, 0);
    issue(1, 1);

    int cs = 0;
#pragma unroll 1
    for (int s = 0; s < NSUP; s++) {
        CP_WAIT1();
        __syncthreads();

        const unsigned base = sb + cs * SSTAGE;

#pragma unroll
        for (int kk2 = 0; kk2 < 4; kk2++) {
            const int half = kk2 >> 1, kkk = kk2 & 1;
            const unsigned A0_ = base + half * 8192;
            const unsigned A1_ = A0_ + PART;
            const unsigned B_  = A0_ + 2 * PART;
            unsigned ah[2][4], al[2][4];
            ldmat4(ah[0], A0_ + (m0     ) * 64 + laA[kkk]);
            ldmat4(ah[1], A0_ + (m0 + 16) * 64 + laA[kkk]);
            ldmat4(al[0], A1_ + (m0     ) * 64 + laA[kkk]);
            ldmat4(al[1], A1_ + (m0 + 16) * 64 + laA[kkk]);
#pragma unroll
            for (int nt2 = 0; nt2 < 4; nt2++) {
                unsigned bu[4];
                ldmat4(bu, B_ + (n0 + nt2 * 16) * 64 + lbB[kkk]);
                // W_hi * B
                mma16816(acc[0][nt2 * 2 + 0], ah[0], bu[0], bu[1]);
                mma16816(acc[0][nt2 * 2 + 1], ah[0], bu[2], bu[3]);
                mma16816(acc[1][nt2 * 2 + 0], ah[1], bu[0], bu[1]);
                mma16816(acc[1][nt2 * 2 + 1], ah[1], bu[2], bu[3]);
                // W_lo * B
                mma16816(acc[0][nt2 * 2 + 0], al[0], bu[0], bu[1]);
                mma16816(acc[0][nt2 * 2 + 1], al[0], bu[2], bu[3]);
                mma16816(acc[1][nt2 * 2 + 0], al[1], bu[0], bu[1]);
                mma16816(acc[1][nt2 * 2 + 1], al[1], bu[2], bu[3]);
            }
        }

        __syncthreads();           // all warps done reading stage cs
        issue(s + 2, cs);          // refill it
        cs ^= 1;
    }

    // ---- epilogue ----
    const int g = lane >> 2, tig = lane & 3;
#pragma unroll
    for (int mi = 0; mi < 2; mi++) {
#pragma unroll
        for (int pr = 0; pr < 2; pr++) {
            const int o = bO + m0 + mi * 16 + g + pr * 8;
            float bs = 0.f;
            if (EPI >= 1) bs = (!GUARDA || o < OROWS) ? bias[o] : 0.f;
#pragma unroll
            for (int nt = 0; nt < 8; nt++) {
                const int t = bT + n0 + nt * 8 + 2 * tig;
                float v0 = acc[mi][nt][pr * 2 + 0] + bs;
                float v1 = acc[mi][nt][pr * 2 + 1] + bs;
                if (EPI == 3) {
                    if (!GUARDA || o < OROWS) {
                        const float mk0 = mask[(size_t)b * Tq + t];
                        const float mk1 = mask[(size_t)b * Tq + t + 1];
                        *(float2*)(OF + ((size_t)b * OROWS + o) * Tq + t) =
                            make_float2(v0 * mk0, v1 * mk1);
                    }
                } else {
                    const size_t i0 = ((size_t)b * Tq + t) * OSTR + o;
                    if (EPI == 2) {
                        const float mk0 = mask[(size_t)b * Tq + t];
                        const float mk1 = mask[(size_t)b * Tq + t + 1];
                        v0 = (__half2float(Resid[i0])        + v0) * mk0;
                        v1 = (__half2float(Resid[i0 + OSTR]) + v1) * mk1;
                    }
                    Out[i0]        = __float2half_rn(v0);
                    Out[i0 + OSTR] = __float2half_rn(v1);
                }
            }
        }
    }
}

// ---------------------------------------------------------------------------
// x transpose: [B, DIN, T] fp32 -> [B, T, DIN] fp16
// ---------------------------------------------------------------------------
__global__ __launch_bounds__(256)
void xpose_kernel(const float* __restrict__ x, __half* __restrict__ xo)
{
    __shared__ float s[32][33];
    const int t0 = blockIdx.x * 32, i0 = blockIdx.y * 32, b = blockIdx.z;
    const int tx = threadIdx.x & 31, ty = threadIdx.x >> 5;
    const float* xb = x + (size_t)b * DINq * Tq;
#pragma unroll
    for (int kk = 0; kk < 4; kk++)
        s[ty + 8 * kk][tx] = xb[(size_t)(i0 + ty + 8 * kk) * Tq + t0 + tx];
    __syncthreads();
#pragma unroll
    for (int kk = 0; kk < 4; kk++) {
        const size_t idx = ((size_t)b * Tq + t0 + ty + 8 * kk) * DINq + i0 + tx;
        xo[idx] = __float2half_rn(s[tx][ty + 8 * kk]);
    }
}

// ---------------------------------------------------------------------------
// Weight split: 22 fp32 matrices -> fp16 hi/lo
// ---------------------------------------------------------------------------
struct WPtrs { const float* p[22]; };

__global__ __launch_bounds__(256)
void convw_kernel(WPtrs wp, __half* __restrict__ wh, __half* __restrict__ wl)
{
    const int idx = blockIdx.x * 256 + threadIdx.x;
    int off = 0;
#pragma unroll
    for (int m = 0; m < 22; m++) {
        const int sz = (m == 0) ? 262144 : ((m == 21) ? NCq * DMq : 65536);
        if (idx < off + sz) {
            __half h, l;
            splitw(wp.p[m][idx - off], h, l);
            wh[idx] = h; wl[idx] = l;
            return;
        }
        off += sz;
    }
}

// ---------------------------------------------------------------------------
// Dilated 3-tap softmax attention + ReLU on fp16 qkv [B,T,768]
// ---------------------------------------------------------------------------
__device__ __forceinline__ void load4h(const __half* __restrict__ p, size_t e, float (&o)[4])
{
    const __half2 a = *(const __half2*)(p + e);
    const __half2 c = *(const __half2*)(p + e + 2);
    o[0] = __low2float(a); o[1] = __high2float(a);
    o[2] = __low2float(c); o[3] = __high2float(c);
}

__device__ __forceinline__ float attn1(float q, float k0, float k1, float k2,
                                       float v0, float v1, float v2)
{
    const float s0 = q * k0, s1 = q * k1, s2 = q * k2;
    const float mx = fmaxf(s0, fmaxf(s1, s2));
    const float e0 = __expf(s0 - mx), e1 = __expf(s1 - mx), e2 = __expf(s2 - mx);
    return fmaxf((e0 * v0 + e1 * v1 + e2 * v2) / (e0 + e1 + e2), 0.f);
}

__global__ __launch_bounds__(256)
void attn_kernel(const __half* __restrict__ qkv, __half* __restrict__ hout, int d)
{
    const size_t gid = (size_t)blockIdx.x * 256 + threadIdx.x;
    const int c4 = (int)(gid & 63);
    const int t  = (int)((gid >> 6) & (Tq - 1));
    const int b  = (int)(gid >> 18);
    const size_t rq = ((size_t)b * Tq + t) * 768 + c4 * 4;
    const long long off = (long long)d * 768;

    float q[4], k1[4], v1[4];
    load4h(qkv, rq,       q);
    load4h(qkv, rq + 256, k1);
    load4h(qkv, rq + 512, v1);
    float k0[4] = {0, 0, 0, 0}, v0[4] = {0, 0, 0, 0};
    float k2[4] = {0, 0, 0, 0}, v2[4] = {0, 0, 0, 0};
    if (t - d >= 0) { load4h(qkv, rq + 256 - off, k0); load4h(qkv, rq + 512 - off, v0); }
    if (t + d < Tq) { load4h(qkv, rq + 256 + off, k2); load4h(qkv, rq + 512 + off, v2); }

    const size_t e = ((size_t)b * Tq + t) * DMq + c4 * 4;
    const __half2 p0 = __floats2half2_rn(
        attn1(q[0], k0[0], k1[0], k2[0], v0[0], v1[0], v2[0]),
        attn1(q[1], k0[1], k1[1], k2[1], v0[1], v1[1], v2[1]));
    const __half2 p1 = __floats2half2_rn(
        attn1(q[2], k0[2], k1[2], k2[2], v0[2], v1[2], v2[2]),
        attn1(q[3], k0[3], k1[3], k2[3], v0[3], v1[3], v2[3]));
    uint2 w;
    w.x = *(const unsigned*)&p0;
    w.y = *(const unsigned*)&p1;
    *(uint2*)(hout + e) = w;
}

// ---------------------------------------------------------------------------
// Launch: batch split B=8 -> 4 streams x 2 batches (fork-join capture pattern)
// ---------------------------------------------------------------------------
#define NSTR 4

extern "C" void kernel_launch(void* const* d_in, const int* in_sizes, int n_in,
                              void* d_out, int out_size)
{
    const float* x    = (const float*)d_in[0];
    const float* mask = (const float*)d_in[1];
    const float* b0b  = (const float*)d_in[3];
    const float* b6b  = (const float*)d_in[30];

    __half *xb, *ob, *qkvb, *hb, *wh, *wl;
    cudaGetSymbolAddress((void**)&xb,   g_x);
    cudaGetSymbolAddress((void**)&ob,   g_o);
    cudaGetSymbolAddress((void**)&qkvb, g_qkv);
    cudaGetSymbolAddress((void**)&hb,   g_h);
    cudaGetSymbolAddress((void**)&wh,   g_wh);
    cudaGetSymbolAddress((void**)&wl,   g_wl);

    cudaFuncSetAttribute(gemm_mma<1, DINq, DMq, DMq>,        cudaFuncAttributeMaxDynamicSharedMemorySize, SMEM_TOT);
    cudaFuncSetAttribute(gemm_mma<0, DMq, 3 * DMq, 3 * DMq>, cudaFuncAttributeMaxDynamicSharedMemorySize, SMEM_TOT);
    cudaFuncSetAttribute(gemm_mma<2, DMq, DMq, DMq>,         cudaFuncAttributeMaxDynamicSharedMemorySize, SMEM_TOT);
    cudaFuncSetAttribute(gemm_mma<3, DMq, NCq, DMq>,         cudaFuncAttributeMaxDynamicSharedMemorySize, SMEM_TOT);

    // split weights (shared by all streams)
    WPtrs wp;
    wp.p[0] = (const float*)d_in[2];
    for (int l = 0; l < 5; l++) {
        wp.p[1 + 4 * l + 0] = (const float*)d_in[4 + 5 * l + 0];
        wp.p[1 + 4 * l + 1] = (const float*)d_in[4 + 5 * l + 1];
        wp.p[1 + 4 * l + 2] = (const float*)d_in[4 + 5 * l + 2];
        wp.p[1 + 4 * l + 3] = (const float*)d_in[4 + 5 * l + 3];
    }
    wp.p[21] = (const float*)d_in[29];
    convw_kernel<<<W_TOTAL / 256, 256>>>(wp, wh, wl);

    // fork worker streams off the main (capture) stream
    cudaStream_t st[NSTR];
    cudaEvent_t ev_fork, ev_join[NSTR];
    for (int s = 0; s < NSTR; s++) cudaStreamCreateWithFlags(&st[s], cudaStreamNonBlocking);
    cudaEventCreateWithFlags(&ev_fork, cudaEventDisableTiming);
    for (int s = 0; s < NSTR; s++) cudaEventCreateWithFlags(&ev_join[s], cudaEventDisableTiming);
    cudaEventRecord(ev_fork, 0);
    for (int s = 0; s < NSTR; s++) cudaStreamWaitEvent(st[s], ev_fork, 0);

    const int dils[5] = {1, 2, 4, 8, 16};
    const int HB = Bq / NSTR;   // 2 batches per stream

    for (int s = 0; s < NSTR; s++) {
        cudaStream_t S = st[s];
        const size_t b0 = (size_t)s * HB;

        const float* x_    = x    + b0 * DINq * Tq;
        const float* mask_ = mask + b0 * Tq;
        __half*      xb_   = xb   + b0 * Tq * DINq;
        __half*      ob_   = ob   + b0 * Tq * DMq;
        __half*      qk_   = qkvb + b0 * Tq * 3 * DMq;
        __half*      hb_   = hb   + b0 * Tq * DMq;
        float*       of_   = (float*)d_out + b0 * NCq * Tq;

        const dim3 thr(256);
        const dim3 g_xp (Tq / 32, DINq / 32, HB);
        const dim3 g_dm (Tq / 128, DMq / 128, HB);
        const dim3 g_qkv(Tq / 128, 3 * DMq / 128, HB);
        const dim3 g_nc (Tq / 128, (NCq + 127) / 128, HB);
        const int  g_at = (HB * Tq * 64) / 256;

        xpose_kernel<<<g_xp, thr, 0, S>>>(x_, xb_);

        gemm_mma<1, DINq, DMq, DMq><<<g_dm, thr, SMEM_TOT, S>>>(
            wh + W_B0, wl + W_B0, xb_, b0b, nullptr, nullptr, ob_, nullptr);

        for (int l = 0; l < 5; l++) {
            const float* bb = (const float*)d_in[4 + 5 * l + 4];
            const int wqkv = W_L0 + l * W_PERL;
            const int bw   = wqkv + 3 * 65536;

            gemm_mma<0, DMq, 3 * DMq, 3 * DMq><<<g_qkv, thr, SMEM_TOT, S>>>(
                wh + wqkv, wl + wqkv, ob_, nullptr, nullptr, nullptr, qk_, nullptr);

            attn_kernel<<<g_at, thr, 0, S>>>(qk_, hb_, dils[l]);

            gemm_mma<2, DMq, DMq, DMq><<<g_dm, thr, SMEM_TOT, S>>>(
                wh + bw, wl + bw, hb_, bb, mask_, ob_, ob_, nullptr);
        }

        gemm_mma<3, DMq, NCq, DMq><<<g_nc, thr, SMEM_TOT, S>>>(
            wh + W_B6, wl + W_B6, ob_, b6b, mask_, nullptr, nullptr, of_);
    }

    // join all streams back into the main stream
    for (int s = 0; s < NSTR; s++) {
        cudaEventRecord(ev_join[s], st[s]);
        cudaStreamWaitEvent(0, ev_join[s], 0);
    }

    cudaEventDestroy(ev_fork);
    for (int s = 0; s < NSTR; s++) {
        cudaEventDestroy(ev_join[s]);
        cudaStreamDestroy(st[s]);
    }
}